// round 1
// baseline (speedup 1.0000x reference)
#include <cuda_runtime.h>
#include <math.h>

// Problem constants
#define MROWS 8192      // B*S
#define DDIM  512       // D = H*KH
#define HNUM  8
#define KHD   64
#define FFD   2048
#define ENUM  4
#define SLEN  1024
#define BNUM  8

// ---------------- scratch (device globals; no allocation allowed) ----------
__device__ float g_x  [MROWS * DDIM];
__device__ float g_q  [MROWS * DDIM];
__device__ float g_k  [MROWS * DDIM];
__device__ float g_v  [MROWS * DDIM];
__device__ float g_att[MROWS * DDIM];
__device__ float g_t1 [MROWS * DDIM];
__device__ float g_ff [MROWS * FFD];
__device__ float g_h  [MROWS * DDIM];
__device__ float g_acc[MROWS * DDIM];
__device__ int   g_idx[MROWS];

// ---------------- embedding gather ----------------
__global__ void k_gather(const int* __restrict__ tok,
                         const float* __restrict__ emb,
                         float* __restrict__ x)
{
    int t  = blockIdx.x * blockDim.x + threadIdx.x;   // over MROWS * DDIM/4
    int i  = t >> 7;                                   // / (DDIM/4)
    int d4 = t & 127;
    const float4* src = (const float4*)(emb + (size_t)tok[i] * DDIM);
    ((float4*)(x + (size_t)i * DDIM))[d4] = src[d4];
}

// ---------------- tiled SGEMM: C = (mask?A:0) @ B (+ C if accum) ----------
// A [M,K] row-major, B [K,N] row-major, C [M,N] row-major.
// M%128==0, N%128==0, K%8==0 assumed (true for all call sites).
// If midx != nullptr, row r of A is zeroed unless midx[r]==expert.
__global__ __launch_bounds__(256)
void k_sgemm(const float* __restrict__ A, const float* __restrict__ Bm,
             float* __restrict__ C, int M, int N, int K,
             const int* __restrict__ midx, int expert, int accum)
{
    const int BM = 128, BN = 128, BK = 8, TM = 8, TN = 8;
    __shared__ float As[BK][BM];
    __shared__ float Bs[BK][BN];

    int tid      = threadIdx.x;
    int cRowBase = blockIdx.y * BM;
    int cColBase = blockIdx.x * BN;
    int tCol     = (tid & 15) * TN;     // 16 thread-cols
    int tRow     = (tid >> 4) * TM;     // 16 thread-rows

    int aRow = tid >> 1;                // 0..127
    int aCol = (tid & 1) * 4;           // 0 or 4
    int bRow = tid >> 5;                // 0..7
    int bCol = (tid & 31) * 4;          // 0..124

    const float* Aptr = A  + (size_t)(cRowBase + aRow) * K + aCol;
    const float* Bptr = Bm + (size_t)bRow * N + cColBase + bCol;

    float mscale = 1.0f;
    if (midx) mscale = (midx[cRowBase + aRow] == expert) ? 1.0f : 0.0f;

    float acc[TM][TN];
#pragma unroll
    for (int i = 0; i < TM; i++)
#pragma unroll
        for (int j = 0; j < TN; j++) acc[i][j] = 0.0f;

    for (int k0 = 0; k0 < K; k0 += BK) {
        float4 a4 = *(const float4*)Aptr;  Aptr += BK;
        float4 b4 = *(const float4*)Bptr;  Bptr += (size_t)BK * N;

        As[aCol + 0][aRow] = a4.x * mscale;
        As[aCol + 1][aRow] = a4.y * mscale;
        As[aCol + 2][aRow] = a4.z * mscale;
        As[aCol + 3][aRow] = a4.w * mscale;
        *(float4*)&Bs[bRow][bCol] = b4;
        __syncthreads();

#pragma unroll
        for (int kk = 0; kk < BK; kk++) {
            float ar[TM], br[TN];
#pragma unroll
            for (int i = 0; i < TM; i++) ar[i] = As[kk][tRow + i];
#pragma unroll
            for (int j = 0; j < TN; j++) br[j] = Bs[kk][tCol + j];
#pragma unroll
            for (int i = 0; i < TM; i++)
#pragma unroll
                for (int j = 0; j < TN; j++)
                    acc[i][j] = fmaf(ar[i], br[j], acc[i][j]);
        }
        __syncthreads();
    }

#pragma unroll
    for (int i = 0; i < TM; i++) {
        float* Crow = C + (size_t)(cRowBase + tRow + i) * N + cColBase + tCol;
        if (accum) {
#pragma unroll
            for (int j = 0; j < TN; j++) Crow[j] += acc[i][j];
        } else {
            float4 v0 = make_float4(acc[i][0], acc[i][1], acc[i][2], acc[i][3]);
            float4 v1 = make_float4(acc[i][4], acc[i][5], acc[i][6], acc[i][7]);
            *(float4*)(Crow)     = v0;
            *(float4*)(Crow + 4) = v1;
        }
    }
}

// ---------------- flash attention (no mask on logits; scale=1/8) ----------
// Q/K/V/O layout: [B*S, H*KH] row-major, head h at cols [h*64, h*64+64).
// grid: (SLEN/128, BNUM*HNUM), block 128; thread owns one query row.
__global__ __launch_bounds__(128)
void k_attn(const float* __restrict__ Q, const float* __restrict__ Kb,
            const float* __restrict__ V, float* __restrict__ O)
{
    const int KT = 32;
    __shared__ float Ks[KT][KHD];
    __shared__ float Vs[KT][KHD];

    int bh = blockIdx.y;
    int b  = bh / HNUM, h = bh % HNUM;
    int qrow = blockIdx.x * 128 + threadIdx.x;       // 0..1023 within batch

    const float* qptr = Q + ((size_t)(b * SLEN + qrow)) * DDIM + h * KHD;
    float q[KHD];
#pragma unroll
    for (int d = 0; d < KHD; d++) q[d] = qptr[d] * 0.125f;  // 1/sqrt(64)

    float o[KHD];
#pragma unroll
    for (int d = 0; d < KHD; d++) o[d] = 0.0f;
    float m = -INFINITY, l = 0.0f;

    for (int kt = 0; kt < SLEN; kt += KT) {
#pragma unroll
        for (int it = 0; it < (KT * KHD) / (128 * 4); it++) {   // 4 passes
            int idx = (it * 128 + threadIdx.x) * 4;
            int r = idx >> 6, c = idx & 63;
            size_t off = ((size_t)(b * SLEN + kt + r)) * DDIM + h * KHD + c;
            *(float4*)&Ks[r][c] = *(const float4*)(Kb + off);
            *(float4*)&Vs[r][c] = *(const float4*)(V + off);
        }
        __syncthreads();

        float s[KT];
#pragma unroll
        for (int j = 0; j < KT; j++) {
            float a = 0.0f;
#pragma unroll
            for (int d = 0; d < KHD; d++) a = fmaf(q[d], Ks[j][d], a);
            s[j] = a;
        }
        float tmax = s[0];
#pragma unroll
        for (int j = 1; j < KT; j++) tmax = fmaxf(tmax, s[j]);
        float mnew = fmaxf(m, tmax);
        float corr = __expf(m - mnew);      // exp(-inf)=0 on first tile
        l *= corr;
#pragma unroll
        for (int d = 0; d < KHD; d++) o[d] *= corr;
#pragma unroll
        for (int j = 0; j < KT; j++) {
            float p = __expf(s[j] - mnew);
            l += p;
#pragma unroll
            for (int d = 0; d < KHD; d++) o[d] = fmaf(p, Vs[j][d], o[d]);
        }
        m = mnew;
        __syncthreads();
    }

    float inv = 1.0f / l;
    float* optr = O + ((size_t)(b * SLEN + qrow)) * DDIM + h * KHD;
#pragma unroll
    for (int d = 0; d < KHD; d++) optr[d] = o[d] * inv;
}

// ---------------- gate = h @ Wg, argmax (first-max like jnp.argmax) -------
__global__ void k_gate(const float* __restrict__ Hm, const float* __restrict__ Wg,
                       int* __restrict__ idx)
{
    int warp = (blockIdx.x * blockDim.x + threadIdx.x) >> 5;
    int lane = threadIdx.x & 31;
    if (warp >= MROWS) return;
    const float* hr = Hm + (size_t)warp * DDIM;
    float g[ENUM] = {0, 0, 0, 0};
    for (int d = lane; d < DDIM; d += 32) {
        float hv = hr[d];
#pragma unroll
        for (int e = 0; e < ENUM; e++) g[e] = fmaf(hv, Wg[d * ENUM + e], g[e]);
    }
#pragma unroll
    for (int e = 0; e < ENUM; e++)
#pragma unroll
        for (int off = 16; off; off >>= 1)
            g[e] += __shfl_down_sync(0xffffffff, g[e], off);
    if (lane == 0) {
        int best = 0; float bv = g[0];
#pragma unroll
        for (int e = 1; e < ENUM; e++)
            if (g[e] > bv) { bv = g[e]; best = e; }
        idx[warp] = best;
    }
}

// ---------------- final: out[i] = dot(acc[i,:], Wout) ----------------------
__global__ void k_final(const float* __restrict__ Acc, const float* __restrict__ Wout,
                        float* __restrict__ out)
{
    int warp = (blockIdx.x * blockDim.x + threadIdx.x) >> 5;
    int lane = threadIdx.x & 31;
    if (warp >= MROWS) return;
    const float* ar = Acc + (size_t)warp * DDIM;
    float s = 0.0f;
    for (int d = lane; d < DDIM; d += 32) s = fmaf(ar[d], Wout[d], s);
#pragma unroll
    for (int off = 16; off; off >>= 1) s += __shfl_down_sync(0xffffffff, s, off);
    if (lane == 0) out[warp] = s;
}

// ---------------- host orchestration --------------------------------------
static void run_block(const float* act,
                      const float* Wq_, const float* Wk_, const float* Wv_,
                      const float* Wo_, const float* W1_, const float* W2_,
                      const int* midx, int expert,
                      float* outbuf, int accum,
                      float* q, float* k, float* v, float* att,
                      float* t1, float* ff)
{
    dim3 gqkv(DDIM / 128, MROWS / 128);
    dim3 gff1(FFD  / 128, MROWS / 128);
    k_sgemm<<<gqkv, 256>>>(act, Wq_, q, MROWS, DDIM, DDIM, midx, expert, 0);
    k_sgemm<<<gqkv, 256>>>(act, Wk_, k, MROWS, DDIM, DDIM, midx, expert, 0);
    k_sgemm<<<gqkv, 256>>>(act, Wv_, v, MROWS, DDIM, DDIM, midx, expert, 0);
    k_attn<<<dim3(SLEN / 128, BNUM * HNUM), 128>>>(q, k, v, att);
    k_sgemm<<<gqkv, 256>>>(att, Wo_, t1, MROWS, DDIM, DDIM, nullptr, 0, 0);
    k_sgemm<<<gff1, 256>>>(t1, W1_, ff, MROWS, FFD, DDIM, nullptr, 0, 0);
    k_sgemm<<<gqkv, 256>>>(ff, W2_, outbuf, MROWS, DDIM, FFD, nullptr, 0, accum);
}

extern "C" void kernel_launch(void* const* d_in, const int* in_sizes, int n_in,
                              void* d_out, int out_size)
{
    (void)in_sizes; (void)n_in; (void)out_size;
    const int*   tokens = (const int*)  d_in[0];
    const float* emb    = (const float*)d_in[1];
    const float* Wq     = (const float*)d_in[2];
    const float* Wk     = (const float*)d_in[3];
    const float* Wv     = (const float*)d_in[4];
    const float* Wo     = (const float*)d_in[5];
    const float* W1     = (const float*)d_in[6];
    const float* W2     = (const float*)d_in[7];
    const float* Wg     = (const float*)d_in[8];
    const float* eWq    = (const float*)d_in[9];
    const float* eWk    = (const float*)d_in[10];
    const float* eWv    = (const float*)d_in[11];
    const float* eWo    = (const float*)d_in[12];
    const float* eW1    = (const float*)d_in[13];
    const float* eW2    = (const float*)d_in[14];
    const float* Wout   = (const float*)d_in[15];
    float* out = (float*)d_out;

    float *x, *q, *k, *v, *att, *t1, *ff, *h, *acc; int* idx;
    cudaGetSymbolAddress((void**)&x,   g_x);
    cudaGetSymbolAddress((void**)&q,   g_q);
    cudaGetSymbolAddress((void**)&k,   g_k);
    cudaGetSymbolAddress((void**)&v,   g_v);
    cudaGetSymbolAddress((void**)&att, g_att);
    cudaGetSymbolAddress((void**)&t1,  g_t1);
    cudaGetSymbolAddress((void**)&ff,  g_ff);
    cudaGetSymbolAddress((void**)&h,   g_h);
    cudaGetSymbolAddress((void**)&acc, g_acc);
    cudaGetSymbolAddress((void**)&idx, g_idx);

    // 1. embedding gather
    k_gather<<<(MROWS * (DDIM / 4)) / 256, 256>>>(tokens, emb, x);

    // 2. shared transformer block -> h
    run_block(x, Wq, Wk, Wv, Wo, W1, W2, nullptr, 0, h, 0,
              q, k, v, att, t1, ff);

    // 3. gating argmax
    k_gate<<<MROWS / 8, 256>>>(h, Wg, idx);

    // 4. experts: masked input, dense attention, accumulate into acc
    for (int e = 0; e < ENUM; e++) {
        const float* ewq = eWq + (size_t)e * DDIM * DDIM;
        const float* ewk = eWk + (size_t)e * DDIM * DDIM;
        const float* ewv = eWv + (size_t)e * DDIM * DDIM;
        const float* ewo = eWo + (size_t)e * DDIM * DDIM;
        const float* ew1 = eW1 + (size_t)e * DDIM * FFD;
        const float* ew2 = eW2 + (size_t)e * FFD * DDIM;
        run_block(h, ewq, ewk, ewv, ewo, ew1, ew2, idx, e, acc, (e > 0) ? 1 : 0,
                  q, k, v, att, t1, ff);
    }

    // 5. out = acc @ Wout
    k_final<<<MROWS / 8, 256>>>(acc, Wout, out);
}

// round 3
// speedup vs baseline: 1.4360x; 1.4360x over previous
#include <cuda_runtime.h>
#include <cuda_bf16.h>
#include <math.h>
#include <stdint.h>

// Problem constants
#define MROWS 8192      // B*S
#define DDIM  512       // D = H*KH
#define HNUM  8
#define KHD   64
#define FFD   2048
#define ENUM  4
#define SLEN  1024
#define BNUM  8
#define QKVW  1536      // fused q|k|v row width

// ===================== scratch (device globals) ==============================
__device__ float g_x  [MROWS * DDIM];
__device__ float g_qkv[MROWS * QKVW];
__device__ float g_att[MROWS * DDIM];
__device__ float g_t1 [MROWS * DDIM];
__device__ float g_ff [MROWS * FFD];
__device__ float g_h  [MROWS * DDIM];
__device__ float g_acc[MROWS * DDIM];
__device__ int   g_idx[MROWS];
__device__ __nv_bfloat16 g_abf [MROWS * 2 * FFD];            // act hi|lo (max K=2048)
__device__ __nv_bfloat16 g_wqkv[ENUM][QKVW * 2 * DDIM];      // [1536, 1024]
__device__ __nv_bfloat16 g_wo  [ENUM][DDIM * 2 * DDIM];      // [512, 1024]
__device__ __nv_bfloat16 g_w1  [ENUM][FFD  * 2 * DDIM];      // [2048, 1024]
__device__ __nv_bfloat16 g_w2  [ENUM][DDIM * 2 * FFD];       // [512, 4096]

// ===================== PTX helpers (base ISA only) ==========================
__device__ __forceinline__ uint32_t smem_u32(const void* p) {
    uint32_t a;
    asm("{ .reg .u64 t; cvta.to.shared.u64 t, %1; cvt.u32.u64 %0, t; }"
        : "=r"(a) : "l"(p));
    return a;
}
__device__ __forceinline__ void cp16(uint32_t dst, const void* src) {
    asm volatile("cp.async.cg.shared.global [%0], [%1], 16;"
                 :: "r"(dst), "l"(src) : "memory");
}
__device__ __forceinline__ void ldsm_x4(uint32_t& r0, uint32_t& r1,
                                        uint32_t& r2, uint32_t& r3, uint32_t addr) {
    asm volatile("ldmatrix.sync.aligned.m8n8.x4.shared.b16 {%0,%1,%2,%3}, [%4];"
                 : "=r"(r0), "=r"(r1), "=r"(r2), "=r"(r3) : "r"(addr));
}
__device__ __forceinline__ void mma16816(float* c, const uint32_t* a, const uint32_t* b) {
    asm volatile("mma.sync.aligned.m16n8k16.row.col.f32.bf16.bf16.f32 "
                 "{%0,%1,%2,%3}, {%4,%5,%6,%7}, {%8,%9}, {%0,%1,%2,%3};"
                 : "+f"(c[0]), "+f"(c[1]), "+f"(c[2]), "+f"(c[3])
                 : "r"(a[0]), "r"(a[1]), "r"(a[2]), "r"(a[3]),
                   "r"(b[0]), "r"(b[1]));
}

// ===================== embedding gather =====================================
__global__ void k_gather(const int* __restrict__ tok,
                         const float* __restrict__ emb,
                         float* __restrict__ x)
{
    int t  = blockIdx.x * blockDim.x + threadIdx.x;
    int i  = t >> 7;
    int d4 = t & 127;
    const float4* src = (const float4*)(emb + (size_t)tok[i] * DDIM);
    ((float4*)(x + (size_t)i * DDIM))[d4] = src[d4];
}

// ===================== fp32 SGEMM (shared block only) =======================
__global__ __launch_bounds__(256)
void k_sgemm(const float* __restrict__ A, const float* __restrict__ Bm,
             float* __restrict__ C, int N, int K, int ldc)
{
    const int BM = 128, BN = 128, BK = 8, TM = 8, TN = 8;
    __shared__ float As[BK][BM];
    __shared__ float Bs[BK][BN];

    int tid      = threadIdx.x;
    int cRowBase = blockIdx.y * BM;
    int cColBase = blockIdx.x * BN;
    int tCol     = (tid & 15) * TN;
    int tRow     = (tid >> 4) * TM;

    int aRow = tid >> 1;
    int aCol = (tid & 1) * 4;
    int bRow = tid >> 5;
    int bCol = (tid & 31) * 4;

    const float* Aptr = A  + (size_t)(cRowBase + aRow) * K + aCol;
    const float* Bptr = Bm + (size_t)bRow * N + cColBase + bCol;

    float acc[TM][TN];
#pragma unroll
    for (int i = 0; i < TM; i++)
#pragma unroll
        for (int j = 0; j < TN; j++) acc[i][j] = 0.0f;

    for (int k0 = 0; k0 < K; k0 += BK) {
        float4 a4 = *(const float4*)Aptr;  Aptr += BK;
        float4 b4 = *(const float4*)Bptr;  Bptr += (size_t)BK * N;

        As[aCol + 0][aRow] = a4.x;
        As[aCol + 1][aRow] = a4.y;
        As[aCol + 2][aRow] = a4.z;
        As[aCol + 3][aRow] = a4.w;
        *(float4*)&Bs[bRow][bCol] = b4;
        __syncthreads();

#pragma unroll
        for (int kk = 0; kk < BK; kk++) {
            float ar[TM], br[TN];
#pragma unroll
            for (int i = 0; i < TM; i++) ar[i] = As[kk][tRow + i];
#pragma unroll
            for (int j = 0; j < TN; j++) br[j] = Bs[kk][tCol + j];
#pragma unroll
            for (int i = 0; i < TM; i++)
#pragma unroll
                for (int j = 0; j < TN; j++)
                    acc[i][j] = fmaf(ar[i], br[j], acc[i][j]);
        }
        __syncthreads();
    }

#pragma unroll
    for (int i = 0; i < TM; i++) {
        float* Crow = C + (size_t)(cRowBase + tRow + i) * ldc + cColBase + tCol;
        float4 v0 = make_float4(acc[i][0], acc[i][1], acc[i][2], acc[i][3]);
        float4 v1 = make_float4(acc[i][4], acc[i][5], acc[i][6], acc[i][7]);
        *(float4*)(Crow)     = v0;
        *(float4*)(Crow + 4) = v1;
    }
}

// ===================== bf16x3 conversion kernels ============================
// act: fp32 [M,K] (optional row mask) -> bf16 [M, 2K] = [hi | lo]
__global__ void k_cvt_act(const float* __restrict__ X, __nv_bfloat16* __restrict__ Y,
                          int total, int K, const int* __restrict__ midx, int e)
{
    int i = blockIdx.x * blockDim.x + threadIdx.x;
    if (i >= total) return;
    int r = i / K, c = i - r * K;
    float x = X[i];
    if (midx && midx[r] != e) x = 0.0f;
    __nv_bfloat16 hi = __float2bfloat16(x);
    float lo = x - __bfloat162float(hi);
    size_t base = (size_t)r * (2 * K) + c;
    Y[base]     = hi;
    Y[base + K] = __float2bfloat16(lo);
}

// weight: fp32 [K,N] -> bf16 [N, 2K] transposed split
__global__ void k_cvt_wt(const float* __restrict__ W, __nv_bfloat16* __restrict__ Y,
                         int K, int N)
{
    __shared__ float tile[32][33];
    int k0 = blockIdx.y * 32, n0 = blockIdx.x * 32;
    int tx = threadIdx.x, ty = threadIdx.y;   // 32 x 8
#pragma unroll
    for (int i = 0; i < 32; i += 8)
        tile[ty + i][tx] = W[(size_t)(k0 + ty + i) * N + n0 + tx];
    __syncthreads();
#pragma unroll
    for (int i = 0; i < 32; i += 8) {
        float x = tile[tx][ty + i];
        __nv_bfloat16 hi = __float2bfloat16(x);
        float lo = x - __bfloat162float(hi);
        size_t base = (size_t)(n0 + ty + i) * (2 * K) + k0 + tx;
        Y[base]     = hi;
        Y[base + K] = __float2bfloat16(lo);
    }
}

// ===================== mma.sync bf16x3 GEMM =================================
// C[M,N] fp32 (ldc=N) = 3-pass bf16 emulated fp32: A[M,2K] x B[N,2K] (K-major)
// Block tile 128x128, BK=32, 8 warps (2m x 4n), warp tile 64x32.
// 3-stage cp.async pipeline; stage = 8KB A + 8KB B.
#define G3_STAGE 16384
#define G3_SMEM  (3 * G3_STAGE)

__global__ __launch_bounds__(256)
void k_gemm3(const __nv_bfloat16* __restrict__ Ag,
             const __nv_bfloat16* __restrict__ Bg,
             float* __restrict__ C, int N, int K, int accum)
{
    extern __shared__ __align__(128) unsigned char smem[];
    const uint32_t sbase = smem_u32(smem);
    const int tid  = threadIdx.x;
    const int wid  = tid >> 5;
    const int lane = tid & 31;

    const int mbase = blockIdx.y * 128;
    const int nbase = blockIdx.x * 128;
    const int K2    = 2 * K;
    const int NCP   = K / 32;        // chunks per pass
    const int NC    = 3 * NCP;

    const int mo = (wid >> 2) * 64;  // warp m offset within tile
    const int no = (wid & 3) * 32;   // warp n offset within tile

    // fill chunk c into stage c%3
    auto fill = [&](int c) {
        int s  = c % 3;
        int p  = c / NCP, ck = c - p * NCP;
        int acol = ((p == 2) ? K : 0) + ck * 32;
        int bcol = ((p == 1) ? K : 0) + ck * 32;
        uint32_t sAo = sbase + s * G3_STAGE;
        uint32_t sBo = sAo + 8192;
#pragma unroll
        for (int i = 0; i < 2; i++) {
            int ch = tid + i * 256;          // 0..511
            int r  = ch >> 2, cc = ch & 3;
            uint32_t sw = (uint32_t)((cc ^ ((r >> 1) & 3)) << 4);
            cp16(sAo + r * 64 + sw, Ag + (size_t)(mbase + r) * K2 + acol + cc * 8);
            cp16(sBo + r * 64 + sw, Bg + (size_t)(nbase + r) * K2 + bcol + cc * 8);
        }
        asm volatile("cp.async.commit_group;" ::: "memory");
    };

    float acc[4][4][4];
#pragma unroll
    for (int i = 0; i < 4; i++)
#pragma unroll
        for (int j = 0; j < 4; j++)
#pragma unroll
            for (int t = 0; t < 4; t++) acc[i][j][t] = 0.0f;

    fill(0);
    fill(1);

    for (int c = 0; c < NC; c++) {
        if (c + 1 < NC) asm volatile("cp.async.wait_group 1;" ::: "memory");
        else            asm volatile("cp.async.wait_group 0;" ::: "memory");
        __syncthreads();

        uint32_t sAo = sbase + (c % 3) * G3_STAGE;
        uint32_t sBo = sAo + 8192;

#pragma unroll
        for (int kk = 0; kk < 2; kk++) {
            uint32_t a[4][4];
#pragma unroll
            for (int i = 0; i < 4; i++) {
                int row = mo + i * 16 + (lane & 15);
                int chk = 2 * kk + (lane >> 4);
                uint32_t addr = sAo + row * 64 + (uint32_t)(((chk ^ ((row >> 1) & 3))) << 4);
                ldsm_x4(a[i][0], a[i][1], a[i][2], a[i][3], addr);
            }
            uint32_t b[4][2];
#pragma unroll
            for (int jj = 0; jj < 2; jj++) {
                int nrow = no + jj * 16 + (lane & 7) + ((lane >> 4) << 3);
                int chk  = 2 * kk + ((lane >> 3) & 1);
                uint32_t addr = sBo + nrow * 64 + (uint32_t)(((chk ^ ((nrow >> 1) & 3))) << 4);
                ldsm_x4(b[2 * jj][0], b[2 * jj][1], b[2 * jj + 1][0], b[2 * jj + 1][1], addr);
            }
#pragma unroll
            for (int i = 0; i < 4; i++)
#pragma unroll
                for (int j = 0; j < 4; j++)
                    mma16816(acc[i][j], a[i], b[j]);
        }

        __syncthreads();
        if (c + 2 < NC) fill(c + 2);
    }

    // epilogue: thread t of warp holds rows (t/4, t/4+8), cols 2*(t%4)..+1
    int rbase = mbase + mo + (lane >> 2);
    int cbase = nbase + no + (lane & 3) * 2;
#pragma unroll
    for (int i = 0; i < 4; i++) {
#pragma unroll
        for (int j = 0; j < 4; j++) {
            float* p0 = C + (size_t)(rbase + i * 16)     * N + cbase + j * 8;
            float* p1 = C + (size_t)(rbase + i * 16 + 8) * N + cbase + j * 8;
            if (accum) {
                p0[0] += acc[i][j][0];  p0[1] += acc[i][j][1];
                p1[0] += acc[i][j][2];  p1[1] += acc[i][j][3];
            } else {
                *(float2*)p0 = make_float2(acc[i][j][0], acc[i][j][1]);
                *(float2*)p1 = make_float2(acc[i][j][2], acc[i][j][3]);
            }
        }
    }
}

// ===================== flash attention (fp32, fused qkv layout) =============
// QKV [M, 1536]: q at col 0, k at 512, v at 1024; head h at +h*64.
__global__ __launch_bounds__(128)
void k_attn(const float* __restrict__ QKV, float* __restrict__ O)
{
    const int KT = 32;
    __shared__ float Ks[KT][KHD];
    __shared__ float Vs[KT][KHD];

    int bh = blockIdx.y;
    int b  = bh / HNUM, h = bh % HNUM;
    int qrow = blockIdx.x * 128 + threadIdx.x;

    const float* qptr = QKV + (size_t)(b * SLEN + qrow) * QKVW + h * KHD;
    float q[KHD];
#pragma unroll
    for (int d = 0; d < KHD; d++) q[d] = qptr[d] * 0.125f;

    float o[KHD];
#pragma unroll
    for (int d = 0; d < KHD; d++) o[d] = 0.0f;
    float m = -INFINITY, l = 0.0f;

    for (int kt = 0; kt < SLEN; kt += KT) {
#pragma unroll
        for (int it = 0; it < (KT * KHD) / (128 * 4); it++) {
            int idx = (it * 128 + threadIdx.x) * 4;
            int r = idx >> 6, c = idx & 63;
            size_t off = (size_t)(b * SLEN + kt + r) * QKVW + h * KHD + c;
            *(float4*)&Ks[r][c] = *(const float4*)(QKV + off + DDIM);
            *(float4*)&Vs[r][c] = *(const float4*)(QKV + off + 2 * DDIM);
        }
        __syncthreads();

        float s[KT];
#pragma unroll
        for (int j = 0; j < KT; j++) {
            float a = 0.0f;
#pragma unroll
            for (int d = 0; d < KHD; d++) a = fmaf(q[d], Ks[j][d], a);
            s[j] = a;
        }
        float tmax = s[0];
#pragma unroll
        for (int j = 1; j < KT; j++) tmax = fmaxf(tmax, s[j]);
        float mnew = fmaxf(m, tmax);
        float corr = __expf(m - mnew);
        l *= corr;
#pragma unroll
        for (int d = 0; d < KHD; d++) o[d] *= corr;
#pragma unroll
        for (int j = 0; j < KT; j++) {
            float p = __expf(s[j] - mnew);
            l += p;
#pragma unroll
            for (int d = 0; d < KHD; d++) o[d] = fmaf(p, Vs[j][d], o[d]);
        }
        m = mnew;
        __syncthreads();
    }

    float inv = 1.0f / l;
    float* optr = O + (size_t)(b * SLEN + qrow) * DDIM + h * KHD;
#pragma unroll
    for (int d = 0; d < KHD; d++) optr[d] = o[d] * inv;
}

// ===================== gate argmax ==========================================
__global__ void k_gate(const float* __restrict__ Hm, const float* __restrict__ Wg,
                       int* __restrict__ idx)
{
    int warp = (blockIdx.x * blockDim.x + threadIdx.x) >> 5;
    int lane = threadIdx.x & 31;
    if (warp >= MROWS) return;
    const float* hr = Hm + (size_t)warp * DDIM;
    float g[ENUM] = {0, 0, 0, 0};
    for (int d = lane; d < DDIM; d += 32) {
        float hv = hr[d];
#pragma unroll
        for (int e = 0; e < ENUM; e++) g[e] = fmaf(hv, Wg[d * ENUM + e], g[e]);
    }
#pragma unroll
    for (int e = 0; e < ENUM; e++)
#pragma unroll
        for (int off = 16; off; off >>= 1)
            g[e] += __shfl_down_sync(0xffffffff, g[e], off);
    if (lane == 0) {
        int best = 0; float bv = g[0];
#pragma unroll
        for (int e = 1; e < ENUM; e++)
            if (g[e] > bv) { bv = g[e]; best = e; }
        idx[warp] = best;
    }
}

// ===================== final Wout dot =======================================
__global__ void k_final(const float* __restrict__ Acc, const float* __restrict__ Wout,
                        float* __restrict__ out)
{
    int warp = (blockIdx.x * blockDim.x + threadIdx.x) >> 5;
    int lane = threadIdx.x & 31;
    if (warp >= MROWS) return;
    const float* ar = Acc + (size_t)warp * DDIM;
    float s = 0.0f;
    for (int d = lane; d < DDIM; d += 32) s = fmaf(ar[d], Wout[d], s);
#pragma unroll
    for (int off = 16; off; off >>= 1) s += __shfl_down_sync(0xffffffff, s, off);
    if (lane == 0) out[warp] = s;
}

// ===================== host orchestration ===================================
extern "C" void kernel_launch(void* const* d_in, const int* in_sizes, int n_in,
                              void* d_out, int out_size)
{
    (void)in_sizes; (void)n_in; (void)out_size;
    const int*   tokens = (const int*)  d_in[0];
    const float* emb    = (const float*)d_in[1];
    const float* Wq     = (const float*)d_in[2];
    const float* Wk     = (const float*)d_in[3];
    const float* Wv     = (const float*)d_in[4];
    const float* Wo     = (const float*)d_in[5];
    const float* W1     = (const float*)d_in[6];
    const float* W2     = (const float*)d_in[7];
    const float* Wg     = (const float*)d_in[8];
    const float* eWq    = (const float*)d_in[9];
    const float* eWk    = (const float*)d_in[10];
    const float* eWv    = (const float*)d_in[11];
    const float* eWo    = (const float*)d_in[12];
    const float* eW1    = (const float*)d_in[13];
    const float* eW2    = (const float*)d_in[14];
    const float* Wout   = (const float*)d_in[15];
    float* out = (float*)d_out;

    float *x, *qkv, *att, *t1, *ff, *h, *acc; int* idx;
    __nv_bfloat16 *abf, *wqkv, *wo, *w1, *w2;
    cudaGetSymbolAddress((void**)&x,    g_x);
    cudaGetSymbolAddress((void**)&qkv,  g_qkv);
    cudaGetSymbolAddress((void**)&att,  g_att);
    cudaGetSymbolAddress((void**)&t1,   g_t1);
    cudaGetSymbolAddress((void**)&ff,   g_ff);
    cudaGetSymbolAddress((void**)&h,    g_h);
    cudaGetSymbolAddress((void**)&acc,  g_acc);
    cudaGetSymbolAddress((void**)&idx,  g_idx);
    cudaGetSymbolAddress((void**)&abf,  g_abf);
    cudaGetSymbolAddress((void**)&wqkv, g_wqkv);
    cudaGetSymbolAddress((void**)&wo,   g_wo);
    cudaGetSymbolAddress((void**)&w1,   g_w1);
    cudaGetSymbolAddress((void**)&w2,   g_w2);

    cudaFuncSetAttribute(k_gemm3, cudaFuncAttributeMaxDynamicSharedMemorySize, G3_SMEM);

    dim3 tb32(32, 8);

    // -- expert weight conversion (transpose + bf16 hi/lo split) --
    for (int e = 0; e < ENUM; e++) {
        __nv_bfloat16* wq_e = wqkv + (size_t)e * QKVW * 2 * DDIM;
        k_cvt_wt<<<dim3(DDIM / 32, DDIM / 32), tb32>>>(eWq + (size_t)e * DDIM * DDIM,
                                                       wq_e, DDIM, DDIM);
        k_cvt_wt<<<dim3(DDIM / 32, DDIM / 32), tb32>>>(eWk + (size_t)e * DDIM * DDIM,
                                                       wq_e + (size_t)DDIM * 2 * DDIM, DDIM, DDIM);
        k_cvt_wt<<<dim3(DDIM / 32, DDIM / 32), tb32>>>(eWv + (size_t)e * DDIM * DDIM,
                                                       wq_e + (size_t)2 * DDIM * 2 * DDIM, DDIM, DDIM);
        k_cvt_wt<<<dim3(DDIM / 32, DDIM / 32), tb32>>>(eWo + (size_t)e * DDIM * DDIM,
                                                       wo + (size_t)e * DDIM * 2 * DDIM, DDIM, DDIM);
        k_cvt_wt<<<dim3(FFD / 32, DDIM / 32), tb32>>>(eW1 + (size_t)e * DDIM * FFD,
                                                      w1 + (size_t)e * FFD * 2 * DDIM, DDIM, FFD);
        k_cvt_wt<<<dim3(DDIM / 32, FFD / 32), tb32>>>(eW2 + (size_t)e * FFD * DDIM,
                                                      w2 + (size_t)e * DDIM * 2 * FFD, FFD, DDIM);
    }

    // -- 1. embedding gather --
    k_gather<<<(MROWS * (DDIM / 4)) / 256, 256>>>(tokens, emb, x);

    // -- 2. shared block (fp32 to protect the argmax gate) --
    dim3 g512(DDIM / 128, MROWS / 128);
    dim3 gff (FFD  / 128, MROWS / 128);
    k_sgemm<<<g512, 256>>>(x, Wq, qkv,            DDIM, DDIM, QKVW);
    k_sgemm<<<g512, 256>>>(x, Wk, qkv + DDIM,     DDIM, DDIM, QKVW);
    k_sgemm<<<g512, 256>>>(x, Wv, qkv + 2 * DDIM, DDIM, DDIM, QKVW);
    k_attn<<<dim3(SLEN / 128, BNUM * HNUM), 128>>>(qkv, att);
    k_sgemm<<<g512, 256>>>(att, Wo, t1, DDIM, DDIM, DDIM);
    k_sgemm<<<gff,  256>>>(t1,  W1, ff, FFD,  DDIM, FFD);
    k_sgemm<<<g512, 256>>>(ff,  W2, h,  DDIM, FFD,  DDIM);

    // -- 3. gate argmax --
    k_gate<<<MROWS / 8, 256>>>(h, Wg, idx);

    // -- 4. experts (mma.sync bf16x3 GEMMs, dense masked attention) --
    for (int e = 0; e < ENUM; e++) {
        __nv_bfloat16* wq_e = wqkv + (size_t)e * QKVW * 2 * DDIM;
        __nv_bfloat16* wo_e = wo   + (size_t)e * DDIM * 2 * DDIM;
        __nv_bfloat16* w1_e = w1   + (size_t)e * FFD  * 2 * DDIM;
        __nv_bfloat16* w2_e = w2   + (size_t)e * DDIM * 2 * FFD;

        k_cvt_act<<<(MROWS * DDIM + 255) / 256, 256>>>(h, abf, MROWS * DDIM, DDIM, idx, e);
        k_gemm3<<<dim3(QKVW / 128, MROWS / 128), 256, G3_SMEM>>>(abf, wq_e, qkv, QKVW, DDIM, 0);
        k_attn<<<dim3(SLEN / 128, BNUM * HNUM), 128>>>(qkv, att);
        k_cvt_act<<<(MROWS * DDIM + 255) / 256, 256>>>(att, abf, MROWS * DDIM, DDIM, nullptr, 0);
        k_gemm3<<<dim3(DDIM / 128, MROWS / 128), 256, G3_SMEM>>>(abf, wo_e, t1, DDIM, DDIM, 0);
        k_cvt_act<<<(MROWS * DDIM + 255) / 256, 256>>>(t1, abf, MROWS * DDIM, DDIM, nullptr, 0);
        k_gemm3<<<dim3(FFD / 128, MROWS / 128), 256, G3_SMEM>>>(abf, w1_e, ff, FFD, DDIM, 0);
        k_cvt_act<<<(MROWS * FFD + 255) / 256, 256>>>(ff, abf, MROWS * FFD, FFD, nullptr, 0);
        k_gemm3<<<dim3(DDIM / 128, MROWS / 128), 256, G3_SMEM>>>(abf, w2_e, acc, DDIM, FFD, (e > 0) ? 1 : 0);
    }

    // -- 5. out = acc @ Wout --
    k_final<<<MROWS / 8, 256>>>(acc, Wout, out);
}

// round 4
// speedup vs baseline: 1.7996x; 1.2532x over previous
#include <cuda_runtime.h>
#include <cuda_bf16.h>
#include <math.h>
#include <stdint.h>

// Problem constants
#define MROWS 8192      // B*S
#define DDIM  512       // D = H*KH
#define HNUM  8
#define KHD   64
#define FFD   2048
#define ENUM  4
#define SLEN  1024
#define BNUM  8
#define QKVW  1536      // fused q|k|v row width

// ===================== scratch (device globals) ==============================
__device__ float g_x  [MROWS * DDIM];
__device__ float g_qkv[MROWS * QKVW];          // shared qkv, then reused per-expert compact qkv
__device__ float g_att[MROWS * DDIM];
__device__ float g_t1 [MROWS * DDIM];
__device__ float g_ff [MROWS * FFD];
__device__ float g_h  [MROWS * DDIM];
__device__ int   g_idx[MROWS];
__device__ int   g_cnt[ENUM * BNUM];
__device__ int   g_segoff[ENUM * BNUM];
__device__ int   g_ne[ENUM];
__device__ int   g_pos[MROWS];
__device__ float g_meanS[ENUM * BNUM];
__device__ float g_totalS[BNUM];
__device__ __align__(16) unsigned char g_zerobuf[16];   // zero-init cp.async source

// compact buffers (bf16 hi|lo split, row width = 2K)
__device__ __nv_bfloat16 g_cbfA[ENUM * MROWS * 2 * DDIM];  // masked-gathered h split
__device__ __nv_bfloat16 g_catt[MROWS * 2 * DDIM];         // compact attention out split
__device__ __nv_bfloat16 g_ct1 [MROWS * 2 * DDIM];
__device__ __nv_bfloat16 g_cff [MROWS * 2 * FFD];
__device__ float         g_cy  [ENUM * MROWS * DDIM];      // compact expert FFN out

// mean-row buffers (per expert, 128-row padded, only rows 0..7 live)
__device__ __nv_bfloat16 g_mv [ENUM * 128 * 2 * DDIM];
__device__ __nv_bfloat16 g_mt1[ENUM * 128 * 2 * DDIM];
__device__ __nv_bfloat16 g_mff[ENUM * 128 * 2 * FFD];
__device__ float         g_my [ENUM * 128 * DDIM];

// expert weights bf16 split, transposed: [N, 2K]
__device__ __nv_bfloat16 g_wqkv[ENUM * QKVW * 2 * DDIM];
__device__ __nv_bfloat16 g_wo  [ENUM * DDIM * 2 * DDIM];
__device__ __nv_bfloat16 g_w1  [ENUM * FFD  * 2 * DDIM];
__device__ __nv_bfloat16 g_w2  [ENUM * DDIM * 2 * FFD];

// ===================== PTX helpers (base ISA only) ==========================
__device__ __forceinline__ uint32_t smem_u32(const void* p) {
    uint32_t a;
    asm("{ .reg .u64 t; cvta.to.shared.u64 t, %1; cvt.u32.u64 %0, t; }"
        : "=r"(a) : "l"(p));
    return a;
}
__device__ __forceinline__ void cp16(uint32_t dst, const void* src) {
    asm volatile("cp.async.cg.shared.global [%0], [%1], 16;"
                 :: "r"(dst), "l"(src) : "memory");
}
__device__ __forceinline__ void ldsm_x4(uint32_t& r0, uint32_t& r1,
                                        uint32_t& r2, uint32_t& r3, uint32_t addr) {
    asm volatile("ldmatrix.sync.aligned.m8n8.x4.shared.b16 {%0,%1,%2,%3}, [%4];"
                 : "=r"(r0), "=r"(r1), "=r"(r2), "=r"(r3) : "r"(addr));
}
__device__ __forceinline__ void mma16816(float* c, const uint32_t* a, const uint32_t* b) {
    asm volatile("mma.sync.aligned.m16n8k16.row.col.f32.bf16.bf16.f32 "
                 "{%0,%1,%2,%3}, {%4,%5,%6,%7}, {%8,%9}, {%0,%1,%2,%3};"
                 : "+f"(c[0]), "+f"(c[1]), "+f"(c[2]), "+f"(c[3])
                 : "r"(a[0]), "r"(a[1]), "r"(a[2]), "r"(a[3]),
                   "r"(b[0]), "r"(b[1]));
}
__device__ __forceinline__ void split_bf16(float x, __nv_bfloat16& hi, __nv_bfloat16& lo) {
    hi = __float2bfloat16(x);
    lo = __float2bfloat16(x - __bfloat162float(hi));
}

// ===================== embedding gather =====================================
__global__ void k_gather(const int* __restrict__ tok,
                         const float* __restrict__ emb,
                         float* __restrict__ x)
{
    int t  = blockIdx.x * blockDim.x + threadIdx.x;
    int i  = t >> 7;
    int d4 = t & 127;
    const float4* src = (const float4*)(emb + (size_t)tok[i] * DDIM);
    ((float4*)(x + (size_t)i * DDIM))[d4] = src[d4];
}

// ===================== fp32 SGEMM (shared block only) =======================
__global__ __launch_bounds__(256)
void k_sgemm(const float* __restrict__ A, const float* __restrict__ Bm,
             float* __restrict__ C, int N, int K, int ldc)
{
    const int BM = 128, BN = 128, BK = 8, TM = 8, TN = 8;
    __shared__ float As[BK][BM];
    __shared__ float Bs[BK][BN];

    int tid      = threadIdx.x;
    int cRowBase = blockIdx.y * BM;
    int cColBase = blockIdx.x * BN;
    int tCol     = (tid & 15) * TN;
    int tRow     = (tid >> 4) * TM;

    int aRow = tid >> 1;
    int aCol = (tid & 1) * 4;
    int bRow = tid >> 5;
    int bCol = (tid & 31) * 4;

    const float* Aptr = A  + (size_t)(cRowBase + aRow) * K + aCol;
    const float* Bptr = Bm + (size_t)bRow * N + cColBase + bCol;

    float acc[TM][TN];
#pragma unroll
    for (int i = 0; i < TM; i++)
#pragma unroll
        for (int j = 0; j < TN; j++) acc[i][j] = 0.0f;

    for (int k0 = 0; k0 < K; k0 += BK) {
        float4 a4 = *(const float4*)Aptr;  Aptr += BK;
        float4 b4 = *(const float4*)Bptr;  Bptr += (size_t)BK * N;

        As[aCol + 0][aRow] = a4.x;
        As[aCol + 1][aRow] = a4.y;
        As[aCol + 2][aRow] = a4.z;
        As[aCol + 3][aRow] = a4.w;
        *(float4*)&Bs[bRow][bCol] = b4;
        __syncthreads();

#pragma unroll
        for (int kk = 0; kk < BK; kk++) {
            float ar[TM], br[TN];
#pragma unroll
            for (int i = 0; i < TM; i++) ar[i] = As[kk][tRow + i];
#pragma unroll
            for (int j = 0; j < TN; j++) br[j] = Bs[kk][tCol + j];
#pragma unroll
            for (int i = 0; i < TM; i++)
#pragma unroll
                for (int j = 0; j < TN; j++)
                    acc[i][j] = fmaf(ar[i], br[j], acc[i][j]);
        }
        __syncthreads();
    }

#pragma unroll
    for (int i = 0; i < TM; i++) {
        float* Crow = C + (size_t)(cRowBase + tRow + i) * ldc + cColBase + tCol;
        float4 v0 = make_float4(acc[i][0], acc[i][1], acc[i][2], acc[i][3]);
        float4 v1 = make_float4(acc[i][4], acc[i][5], acc[i][6], acc[i][7]);
        *(float4*)(Crow)     = v0;
        *(float4*)(Crow + 4) = v1;
    }
}

// ===================== weight conversion (transpose + bf16 split) ===========
__global__ void k_cvt_wt(const float* __restrict__ W, __nv_bfloat16* __restrict__ Y,
                         int K, int N)
{
    __shared__ float tile[32][33];
    int k0 = blockIdx.y * 32, n0 = blockIdx.x * 32;
    int tx = threadIdx.x, ty = threadIdx.y;   // 32 x 8
#pragma unroll
    for (int i = 0; i < 32; i += 8)
        tile[ty + i][tx] = W[(size_t)(k0 + ty + i) * N + n0 + tx];
    __syncthreads();
#pragma unroll
    for (int i = 0; i < 32; i += 8) {
        float x = tile[tx][ty + i];
        __nv_bfloat16 hi, lo; split_bf16(x, hi, lo);
        size_t base = (size_t)(n0 + ty + i) * (2 * K) + k0 + tx;
        Y[base]     = hi;
        Y[base + K] = lo;
    }
}

// ===================== mma.sync bf16x3 GEMM (row-predicated) ================
// C[M,N] fp32 (ldc=N, optional) and/or Y split bf16 [rows, 2N] (optional).
// A rows >= n are treated as zero (cp.async from zero buffer); stores predicated.
#define G3_STAGE 16384
#define G3_SMEM  (3 * G3_STAGE)

__global__ __launch_bounds__(256)
void k_gemm3(const __nv_bfloat16* __restrict__ Ag,
             const __nv_bfloat16* __restrict__ Bg,
             float* __restrict__ Cf, __nv_bfloat16* __restrict__ Y,
             int N, int K, const int* __restrict__ nptr, int nconst)
{
    const int n = nptr ? __ldg(nptr) : nconst;
    const int mbase = blockIdx.y * 128;
    if (mbase >= n) return;

    extern __shared__ __align__(128) unsigned char smem[];
    const uint32_t sbase = smem_u32(smem);
    const int tid  = threadIdx.x;
    const int wid  = tid >> 5;
    const int lane = tid & 31;

    const int nbase = blockIdx.x * 128;
    const int K2    = 2 * K;
    const int NCP   = K / 32;
    const int NC    = 3 * NCP;

    const int mo = (wid >> 2) * 64;
    const int no = (wid & 3) * 32;

    auto fill = [&](int c) {
        int s  = c % 3;
        int p  = c / NCP, ck = c - p * NCP;
        int acol = ((p == 2) ? K : 0) + ck * 32;
        int bcol = ((p == 1) ? K : 0) + ck * 32;
        uint32_t sAo = sbase + s * G3_STAGE;
        uint32_t sBo = sAo + 8192;
#pragma unroll
        for (int i2 = 0; i2 < 2; i2++) {
            int ch = tid + i2 * 256;
            int r  = ch >> 2, cc = ch & 3;
            uint32_t sw = (uint32_t)((cc ^ ((r >> 1) & 3)) << 4);
            const void* asrc = (mbase + r < n)
                ? (const void*)(Ag + (size_t)(mbase + r) * K2 + acol + cc * 8)
                : (const void*)g_zerobuf;
            cp16(sAo + r * 64 + sw, asrc);
            cp16(sBo + r * 64 + sw, Bg + (size_t)(nbase + r) * K2 + bcol + cc * 8);
        }
        asm volatile("cp.async.commit_group;" ::: "memory");
    };

    float acc[4][4][4];
#pragma unroll
    for (int i = 0; i < 4; i++)
#pragma unroll
        for (int j = 0; j < 4; j++)
#pragma unroll
            for (int t = 0; t < 4; t++) acc[i][j][t] = 0.0f;

    fill(0);
    fill(1);

    for (int c = 0; c < NC; c++) {
        if (c + 1 < NC) asm volatile("cp.async.wait_group 1;" ::: "memory");
        else            asm volatile("cp.async.wait_group 0;" ::: "memory");
        __syncthreads();

        uint32_t sAo = sbase + (c % 3) * G3_STAGE;
        uint32_t sBo = sAo + 8192;

#pragma unroll
        for (int kk = 0; kk < 2; kk++) {
            uint32_t a[4][4];
#pragma unroll
            for (int i = 0; i < 4; i++) {
                int row = mo + i * 16 + (lane & 15);
                int chk = 2 * kk + (lane >> 4);
                uint32_t addr = sAo + row * 64 + (uint32_t)(((chk ^ ((row >> 1) & 3))) << 4);
                ldsm_x4(a[i][0], a[i][1], a[i][2], a[i][3], addr);
            }
            uint32_t b[4][2];
#pragma unroll
            for (int jj = 0; jj < 2; jj++) {
                int nrow = no + jj * 16 + (lane & 7) + ((lane >> 4) << 3);
                int chk  = 2 * kk + ((lane >> 3) & 1);
                uint32_t addr = sBo + nrow * 64 + (uint32_t)(((chk ^ ((nrow >> 1) & 3))) << 4);
                ldsm_x4(b[2 * jj][0], b[2 * jj][1], b[2 * jj + 1][0], b[2 * jj + 1][1], addr);
            }
#pragma unroll
            for (int i = 0; i < 4; i++)
#pragma unroll
                for (int j = 0; j < 4; j++)
                    mma16816(acc[i][j], a[i], b[j]);
        }

        __syncthreads();
        if (c + 2 < NC) fill(c + 2);
    }

    int rbase = mbase + mo + (lane >> 2);
    int cbase = nbase + no + (lane & 3) * 2;
#pragma unroll
    for (int i = 0; i < 4; i++) {
        int r0 = rbase + i * 16, r1 = r0 + 8;
#pragma unroll
        for (int j = 0; j < 4; j++) {
            int col = cbase + j * 8;
            if (Cf) {
                if (r0 < n)
                    *(float2*)(Cf + (size_t)r0 * N + col) = make_float2(acc[i][j][0], acc[i][j][1]);
                if (r1 < n)
                    *(float2*)(Cf + (size_t)r1 * N + col) = make_float2(acc[i][j][2], acc[i][j][3]);
            }
            if (Y) {
                if (r0 < n) {
                    __nv_bfloat16 h0, l0, h1, l1;
                    split_bf16(acc[i][j][0], h0, l0);
                    split_bf16(acc[i][j][1], h1, l1);
                    *(__nv_bfloat162*)(Y + (size_t)r0 * 2 * N + col)     = __halves2bfloat162(h0, h1);
                    *(__nv_bfloat162*)(Y + (size_t)r0 * 2 * N + N + col) = __halves2bfloat162(l0, l1);
                }
                if (r1 < n) {
                    __nv_bfloat16 h0, l0, h1, l1;
                    split_bf16(acc[i][j][2], h0, l0);
                    split_bf16(acc[i][j][3], h1, l1);
                    *(__nv_bfloat162*)(Y + (size_t)r1 * 2 * N + col)     = __halves2bfloat162(h0, h1);
                    *(__nv_bfloat162*)(Y + (size_t)r1 * 2 * N + N + col) = __halves2bfloat162(l0, l1);
                }
            }
        }
    }
}

// ===================== dense flash attention (shared block) =================
__global__ __launch_bounds__(128)
void k_attn(const float* __restrict__ QKV, float* __restrict__ O)
{
    const int KT = 32;
    __shared__ float Ks[KT][KHD];
    __shared__ float Vs[KT][KHD];

    int bh = blockIdx.y;
    int b  = bh / HNUM, h = bh % HNUM;
    int qrow = blockIdx.x * 128 + threadIdx.x;

    const float* qptr = QKV + (size_t)(b * SLEN + qrow) * QKVW + h * KHD;
    float q[KHD];
#pragma unroll
    for (int d = 0; d < KHD; d++) q[d] = qptr[d] * 0.125f;

    float o[KHD];
#pragma unroll
    for (int d = 0; d < KHD; d++) o[d] = 0.0f;
    float m = -INFINITY, l = 0.0f;

    for (int kt = 0; kt < SLEN; kt += KT) {
#pragma unroll
        for (int it = 0; it < (KT * KHD) / (128 * 4); it++) {
            int idx = (it * 128 + threadIdx.x) * 4;
            int r = idx >> 6, c = idx & 63;
            size_t off = (size_t)(b * SLEN + kt + r) * QKVW + h * KHD + c;
            *(float4*)&Ks[r][c] = *(const float4*)(QKV + off + DDIM);
            *(float4*)&Vs[r][c] = *(const float4*)(QKV + off + 2 * DDIM);
        }
        __syncthreads();

        float s[KT];
#pragma unroll
        for (int j = 0; j < KT; j++) {
            float a = 0.0f;
#pragma unroll
            for (int d = 0; d < KHD; d++) a = fmaf(q[d], Ks[j][d], a);
            s[j] = a;
        }
        float tmax = s[0];
#pragma unroll
        for (int j = 1; j < KT; j++) tmax = fmaxf(tmax, s[j]);
        float mnew = fmaxf(m, tmax);
        float corr = __expf(m - mnew);
        l *= corr;
#pragma unroll
        for (int d = 0; d < KHD; d++) o[d] *= corr;
#pragma unroll
        for (int j = 0; j < KT; j++) {
            float p = __expf(s[j] - mnew);
            l += p;
#pragma unroll
            for (int d = 0; d < KHD; d++) o[d] = fmaf(p, Vs[j][d], o[d]);
        }
        m = mnew;
        __syncthreads();
    }

    float inv = 1.0f / l;
    float* optr = O + (size_t)(b * SLEN + qrow) * DDIM + h * KHD;
#pragma unroll
    for (int d = 0; d < KHD; d++) optr[d] = o[d] * inv;
}

// ===================== compact expert attention =============================
// Queries/keys = compact active rows of this expert; masked keys contribute
// exp(0)=1 each -> init state m=0, l=S-cnt. Output written as bf16 hi|lo split.
__global__ __launch_bounds__(128)
void k_attn_c(const float* __restrict__ QKV,
              __nv_bfloat16* __restrict__ Oy,
              const int* __restrict__ cnt8, const int* __restrict__ seg8)
{
    const int KT = 32;
    __shared__ float Ks[KT][KHD];
    __shared__ float Vs[KT][KHD];

    int bh = blockIdx.y;
    int b  = bh / HNUM, h = bh % HNUM;
    int cnt = __ldg(cnt8 + b), seg = __ldg(seg8 + b);
    if (blockIdx.x * 128 >= cnt) return;
    int qidx = blockIdx.x * 128 + threadIdx.x;
    bool qact = qidx < cnt;

    const float* qptr = QKV + (size_t)(seg + (qact ? qidx : 0)) * QKVW + h * KHD;
    float q[KHD];
#pragma unroll
    for (int d = 0; d < KHD; d++) q[d] = qptr[d] * 0.125f;

    float o[KHD];
#pragma unroll
    for (int d = 0; d < KHD; d++) o[d] = 0.0f;
    float m = 0.0f;                       // virtual masked keys have logit 0
    float l = (float)(SLEN - cnt);        // their total weight at m=0

    for (int kt = 0; kt < cnt; kt += KT) {
        int nval = cnt - kt; if (nval > KT) nval = KT;
#pragma unroll
        for (int it = 0; it < (KT * KHD) / (128 * 4); it++) {
            int idx = (it * 128 + threadIdx.x) * 4;
            int r = idx >> 6, c = idx & 63;
            if (r < nval) {
                size_t off = (size_t)(seg + kt + r) * QKVW + h * KHD + c;
                *(float4*)&Ks[r][c] = *(const float4*)(QKV + off + DDIM);
                *(float4*)&Vs[r][c] = *(const float4*)(QKV + off + 2 * DDIM);
            } else {
                *(float4*)&Ks[r][c] = make_float4(0.f, 0.f, 0.f, 0.f);
                *(float4*)&Vs[r][c] = make_float4(0.f, 0.f, 0.f, 0.f);
            }
        }
        __syncthreads();

        float s[KT];
#pragma unroll
        for (int j = 0; j < KT; j++) {
            float a = 0.0f;
#pragma unroll
            for (int d = 0; d < KHD; d++) a = fmaf(q[d], Ks[j][d], a);
            s[j] = (j < nval) ? a : -1e30f;
        }
        float tmax = s[0];
#pragma unroll
        for (int j = 1; j < KT; j++) tmax = fmaxf(tmax, s[j]);
        float mnew = fmaxf(m, tmax);
        float corr = __expf(m - mnew);
        l *= corr;
#pragma unroll
        for (int d = 0; d < KHD; d++) o[d] *= corr;
#pragma unroll
        for (int j = 0; j < KT; j++) {
            float p = __expf(s[j] - mnew);
            l += p;
#pragma unroll
            for (int d = 0; d < KHD; d++) o[d] = fmaf(p, Vs[j][d], o[d]);
        }
        m = mnew;
        __syncthreads();
    }

    if (qact) {
        float inv = 1.0f / l;
        __nv_bfloat16* yrow = Oy + (size_t)(seg + qidx) * (2 * DDIM) + h * KHD;
#pragma unroll
        for (int d = 0; d < KHD; d += 2) {
            float v0 = o[d] * inv, v1 = o[d + 1] * inv;
            __nv_bfloat16 h0, l0, h1, l1;
            split_bf16(v0, h0, l0);
            split_bf16(v1, h1, l1);
            *(__nv_bfloat162*)(yrow + d)        = __halves2bfloat162(h0, h1);
            *(__nv_bfloat162*)(yrow + DDIM + d) = __halves2bfloat162(l0, l1);
        }
    }
}

// ===================== gate argmax ==========================================
__global__ void k_gate(const float* __restrict__ Hm, const float* __restrict__ Wg,
                       int* __restrict__ idx)
{
    int warp = (blockIdx.x * blockDim.x + threadIdx.x) >> 5;
    int lane = threadIdx.x & 31;
    if (warp >= MROWS) return;
    const float* hr = Hm + (size_t)warp * DDIM;
    float g[ENUM] = {0, 0, 0, 0};
    for (int d = lane; d < DDIM; d += 32) {
        float hv = hr[d];
#pragma unroll
        for (int e = 0; e < ENUM; e++) g[e] = fmaf(hv, Wg[d * ENUM + e], g[e]);
    }
#pragma unroll
    for (int e = 0; e < ENUM; e++)
#pragma unroll
        for (int off = 16; off; off >>= 1)
            g[e] += __shfl_down_sync(0xffffffff, g[e], off);
    if (lane == 0) {
        int best = 0; float bv = g[0];
#pragma unroll
        for (int e = 1; e < ENUM; e++)
            if (g[e] > bv) { bv = g[e]; best = e; }
        idx[warp] = best;
    }
}

// ===================== compaction: scan / offsets / gather ==================
__global__ __launch_bounds__(1024)
void k_scan(const int* __restrict__ idx, int* __restrict__ pos, int* __restrict__ cnt)
{
    int e = blockIdx.x, b = blockIdx.y;
    int t = threadIdx.x;
    int token = b * SLEN + t;
    int p = (idx[token] == e) ? 1 : 0;
    int v = p;
#pragma unroll
    for (int o = 1; o < 32; o <<= 1) {
        int u = __shfl_up_sync(0xffffffffu, v, o);
        if ((t & 31) >= o) v += u;
    }
    __shared__ int wsum[32];
    if ((t & 31) == 31) wsum[t >> 5] = v;
    __syncthreads();
    if (t < 32) {
        int w = wsum[t];
#pragma unroll
        for (int o = 1; o < 32; o <<= 1) {
            int u = __shfl_up_sync(0xffffffffu, w, o);
            if (t >= o) w += u;
        }
        wsum[t] = w;
    }
    __syncthreads();
    int incl = v + ((t >= 32) ? wsum[(t >> 5) - 1] : 0);
    if (p) pos[token] = incl - 1;
    if (t == 1023) cnt[e * BNUM + b] = incl;
}

__global__ void k_off(const int* __restrict__ cnt, int* __restrict__ segoff,
                      int* __restrict__ ne)
{
    int e = threadIdx.x;
    if (e < ENUM) {
        int s = 0;
        for (int b = 0; b < BNUM; b++) { segoff[e * BNUM + b] = s; s += cnt[e * BNUM + b]; }
        ne[e] = s;
    }
}

__global__ void k_gatherc(const float* __restrict__ h, const int* __restrict__ idx,
                          const int* __restrict__ pos, const int* __restrict__ segoff,
                          __nv_bfloat16* __restrict__ cbf)
{
    int t = blockIdx.x * blockDim.x + threadIdx.x;
    int i = t >> 7, c4 = t & 127;
    int e = idx[i], b = i / SLEN;
    int slot = segoff[e * BNUM + b] + pos[i];
    float4 x = ((const float4*)(h + (size_t)i * DDIM))[c4];
    float xv[4] = {x.x, x.y, x.z, x.w};
    __nv_bfloat16 hi[4], lo[4];
#pragma unroll
    for (int j = 0; j < 4; j++) split_bf16(xv[j], hi[j], lo[j]);
    __nv_bfloat16* row = cbf + ((size_t)e * MROWS + slot) * (2 * DDIM);
    *(uint64_t*)(row + c4 * 4)        = *(uint64_t*)hi;
    *(uint64_t*)(row + DDIM + c4 * 4) = *(uint64_t*)lo;
}

// ===================== mean-v per (expert batch) ============================
__global__ __launch_bounds__(128)
void k_meanv(const float* __restrict__ QKV, const int* __restrict__ cnt8,
             const int* __restrict__ seg8, __nv_bfloat16* __restrict__ mv)
{
    int b = blockIdx.x;
    int cnt = __ldg(cnt8 + b), seg = __ldg(seg8 + b);
    int c = threadIdx.x * 4;
    float4 s = make_float4(0.f, 0.f, 0.f, 0.f);
    for (int r = 0; r < cnt; r++) {
        float4 v = *(const float4*)(QKV + (size_t)(seg + r) * QKVW + 2 * DDIM + c);
        s.x += v.x; s.y += v.y; s.z += v.z; s.w += v.w;
    }
    const float is = 1.0f / (float)SLEN;
    float vv[4] = {s.x * is, s.y * is, s.z * is, s.w * is};
    __nv_bfloat16* row = mv + (size_t)b * (2 * DDIM);
#pragma unroll
    for (int j = 0; j < 4; j++) {
        __nv_bfloat16 hi, lo; split_bf16(vv[j], hi, lo);
        row[c + j]        = hi;
        row[DDIM + c + j] = lo;
    }
}

// ===================== mean scalars =========================================
__global__ __launch_bounds__(1024)
void k_msum(const float* __restrict__ my, const float* __restrict__ Wout,
            float* __restrict__ meanS, float* __restrict__ totalS)
{
    __shared__ float sh[ENUM * BNUM];
    int w = threadIdx.x >> 5, lane = threadIdx.x & 31;   // w = e*8+b
    const float* row = my + ((size_t)(w >> 3) * 128 + (w & 7)) * DDIM;
    float s = 0.0f;
    for (int d = lane; d < DDIM; d += 32) s = fmaf(row[d], Wout[d], s);
#pragma unroll
    for (int off = 16; off; off >>= 1) s += __shfl_down_sync(0xffffffff, s, off);
    if (lane == 0) { sh[w] = s; meanS[w] = s; }
    __syncthreads();
    if (threadIdx.x < BNUM) {
        float t = 0.0f;
        for (int e = 0; e < ENUM; e++) t += sh[e * BNUM + threadIdx.x];
        totalS[threadIdx.x] = t;
    }
}

// ===================== final: dot + mean corrections ========================
__global__ void k_final2(const float* __restrict__ cy, const int* __restrict__ idx,
                         const int* __restrict__ pos, const int* __restrict__ segoff,
                         const float* __restrict__ Wout, const float* __restrict__ meanS,
                         const float* __restrict__ totalS, float* __restrict__ out)
{
    int warp = (blockIdx.x * blockDim.x + threadIdx.x) >> 5;
    int lane = threadIdx.x & 31;
    if (warp >= MROWS) return;
    int e = idx[warp], b = warp / SLEN;
    int slot = segoff[e * BNUM + b] + pos[warp];
    const float* r = cy + ((size_t)e * MROWS + slot) * DDIM;
    float s = 0.0f;
    for (int d = lane; d < DDIM; d += 32) s = fmaf(r[d], Wout[d], s);
#pragma unroll
    for (int off = 16; off; off >>= 1) s += __shfl_down_sync(0xffffffff, s, off);
    if (lane == 0) out[warp] = s + totalS[b] - meanS[e * BNUM + b];
}

// ===================== host orchestration ===================================
extern "C" void kernel_launch(void* const* d_in, const int* in_sizes, int n_in,
                              void* d_out, int out_size)
{
    (void)in_sizes; (void)n_in; (void)out_size;
    const int*   tokens = (const int*)  d_in[0];
    const float* emb    = (const float*)d_in[1];
    const float* Wq     = (const float*)d_in[2];
    const float* Wk     = (const float*)d_in[3];
    const float* Wv     = (const float*)d_in[4];
    const float* Wo     = (const float*)d_in[5];
    const float* W1     = (const float*)d_in[6];
    const float* W2     = (const float*)d_in[7];
    const float* Wg     = (const float*)d_in[8];
    const float* eWq    = (const float*)d_in[9];
    const float* eWk    = (const float*)d_in[10];
    const float* eWv    = (const float*)d_in[11];
    const float* eWo    = (const float*)d_in[12];
    const float* eW1    = (const float*)d_in[13];
    const float* eW2    = (const float*)d_in[14];
    const float* Wout   = (const float*)d_in[15];
    float* out = (float*)d_out;

    float *x, *qkv, *att, *t1, *ff, *h, *cy, *my, *meanS, *totalS;
    int *idx, *cnt, *segoff, *ne, *pos;
    __nv_bfloat16 *cbfA, *catt, *ct1, *cff, *mv, *mt1, *mff, *wqkv, *wo, *w1, *w2;
    cudaGetSymbolAddress((void**)&x,      g_x);
    cudaGetSymbolAddress((void**)&qkv,    g_qkv);
    cudaGetSymbolAddress((void**)&att,    g_att);
    cudaGetSymbolAddress((void**)&t1,     g_t1);
    cudaGetSymbolAddress((void**)&ff,     g_ff);
    cudaGetSymbolAddress((void**)&h,      g_h);
    cudaGetSymbolAddress((void**)&cy,     g_cy);
    cudaGetSymbolAddress((void**)&my,     g_my);
    cudaGetSymbolAddress((void**)&meanS,  g_meanS);
    cudaGetSymbolAddress((void**)&totalS, g_totalS);
    cudaGetSymbolAddress((void**)&idx,    g_idx);
    cudaGetSymbolAddress((void**)&cnt,    g_cnt);
    cudaGetSymbolAddress((void**)&segoff, g_segoff);
    cudaGetSymbolAddress((void**)&ne,     g_ne);
    cudaGetSymbolAddress((void**)&pos,    g_pos);
    cudaGetSymbolAddress((void**)&cbfA,   g_cbfA);
    cudaGetSymbolAddress((void**)&catt,   g_catt);
    cudaGetSymbolAddress((void**)&ct1,    g_ct1);
    cudaGetSymbolAddress((void**)&cff,    g_cff);
    cudaGetSymbolAddress((void**)&mv,     g_mv);
    cudaGetSymbolAddress((void**)&mt1,    g_mt1);
    cudaGetSymbolAddress((void**)&mff,    g_mff);
    cudaGetSymbolAddress((void**)&wqkv,   g_wqkv);
    cudaGetSymbolAddress((void**)&wo,     g_wo);
    cudaGetSymbolAddress((void**)&w1,     g_w1);
    cudaGetSymbolAddress((void**)&w2,     g_w2);

    cudaFuncSetAttribute(k_gemm3, cudaFuncAttributeMaxDynamicSharedMemorySize, G3_SMEM);

    dim3 tb32(32, 8);

    // -- expert weight conversion (transpose + bf16 hi/lo split) --
    for (int e = 0; e < ENUM; e++) {
        __nv_bfloat16* wq_e = wqkv + (size_t)e * QKVW * 2 * DDIM;
        k_cvt_wt<<<dim3(DDIM / 32, DDIM / 32), tb32>>>(eWq + (size_t)e * DDIM * DDIM,
                                                       wq_e, DDIM, DDIM);
        k_cvt_wt<<<dim3(DDIM / 32, DDIM / 32), tb32>>>(eWk + (size_t)e * DDIM * DDIM,
                                                       wq_e + (size_t)DDIM * 2 * DDIM, DDIM, DDIM);
        k_cvt_wt<<<dim3(DDIM / 32, DDIM / 32), tb32>>>(eWv + (size_t)e * DDIM * DDIM,
                                                       wq_e + (size_t)2 * DDIM * 2 * DDIM, DDIM, DDIM);
        k_cvt_wt<<<dim3(DDIM / 32, DDIM / 32), tb32>>>(eWo + (size_t)e * DDIM * DDIM,
                                                       wo + (size_t)e * DDIM * 2 * DDIM, DDIM, DDIM);
        k_cvt_wt<<<dim3(FFD / 32, DDIM / 32), tb32>>>(eW1 + (size_t)e * DDIM * FFD,
                                                      w1 + (size_t)e * FFD * 2 * DDIM, DDIM, FFD);
        k_cvt_wt<<<dim3(DDIM / 32, FFD / 32), tb32>>>(eW2 + (size_t)e * FFD * DDIM,
                                                      w2 + (size_t)e * DDIM * 2 * FFD, FFD, DDIM);
    }

    // -- 1. embedding gather --
    k_gather<<<(MROWS * (DDIM / 4)) / 256, 256>>>(tokens, emb, x);

    // -- 2. shared block (fp32 to protect the argmax gate) --
    dim3 g512(DDIM / 128, MROWS / 128);
    dim3 gff (FFD  / 128, MROWS / 128);
    k_sgemm<<<g512, 256>>>(x, Wq, qkv,            DDIM, DDIM, QKVW);
    k_sgemm<<<g512, 256>>>(x, Wk, qkv + DDIM,     DDIM, DDIM, QKVW);
    k_sgemm<<<g512, 256>>>(x, Wv, qkv + 2 * DDIM, DDIM, DDIM, QKVW);
    k_attn<<<dim3(SLEN / 128, BNUM * HNUM), 128>>>(qkv, att);
    k_sgemm<<<g512, 256>>>(att, Wo, t1, DDIM, DDIM, DDIM);
    k_sgemm<<<gff,  256>>>(t1,  W1, ff, FFD,  DDIM, FFD);
    k_sgemm<<<g512, 256>>>(ff,  W2, h,  DDIM, FFD,  DDIM);

    // -- 3. gate argmax + compaction metadata --
    k_gate<<<MROWS / 8, 256>>>(h, Wg, idx);
    k_scan<<<dim3(ENUM, BNUM), 1024>>>(idx, pos, cnt);
    k_off<<<1, 32>>>(cnt, segoff, ne);
    k_gatherc<<<(MROWS * (DDIM / 4)) / 256, 256>>>(h, idx, pos, segoff, cbfA);

    // -- 4. experts on compact active rows + linear mean correction --
    for (int e = 0; e < ENUM; e++) {
        __nv_bfloat16* wq_e = wqkv + (size_t)e * QKVW * 2 * DDIM;
        __nv_bfloat16* wo_e = wo   + (size_t)e * DDIM * 2 * DDIM;
        __nv_bfloat16* w1_e = w1   + (size_t)e * FFD  * 2 * DDIM;
        __nv_bfloat16* w2_e = w2   + (size_t)e * DDIM * 2 * FFD;
        __nv_bfloat16* cbfA_e = cbfA + (size_t)e * MROWS * 2 * DDIM;
        __nv_bfloat16* mv_e   = mv  + (size_t)e * 128 * 2 * DDIM;
        __nv_bfloat16* mt1_e  = mt1 + (size_t)e * 128 * 2 * DDIM;
        __nv_bfloat16* mff_e  = mff + (size_t)e * 128 * 2 * FFD;
        float* my_e = my + (size_t)e * 128 * DDIM;
        float* cy_e = cy + (size_t)e * MROWS * DDIM;
        const int* ne_e  = ne + e;
        const int* cnt_e = cnt + e * BNUM;
        const int* seg_e = segoff + e * BNUM;

        // compact qkv projection (fp32 out for attention)
        k_gemm3<<<dim3(QKVW / 128, MROWS / 128), 256, G3_SMEM>>>(
            cbfA_e, wq_e, qkv, nullptr, QKVW, DDIM, ne_e, 0);
        // compact attention with virtual masked keys (split out)
        k_attn_c<<<dim3(SLEN / 128, BNUM * HNUM), 128>>>(qkv, catt, cnt_e, seg_e);
        // per-batch mean-v rows (split)
        k_meanv<<<BNUM, 128>>>(qkv, cnt_e, seg_e, mv_e);
        // compact FFN chain
        k_gemm3<<<dim3(DDIM / 128, MROWS / 128), 256, G3_SMEM>>>(
            catt, wo_e, nullptr, ct1, DDIM, DDIM, ne_e, 0);
        k_gemm3<<<dim3(FFD / 128, MROWS / 128), 256, G3_SMEM>>>(
            ct1, w1_e, nullptr, cff, FFD, DDIM, ne_e, 0);
        k_gemm3<<<dim3(DDIM / 128, MROWS / 128), 256, G3_SMEM>>>(
            cff, w2_e, cy_e, nullptr, DDIM, FFD, ne_e, 0);
        // mean-row FFN chain (8 live rows)
        k_gemm3<<<dim3(DDIM / 128, 1), 256, G3_SMEM>>>(
            mv_e, wo_e, nullptr, mt1_e, DDIM, DDIM, nullptr, BNUM);
        k_gemm3<<<dim3(FFD / 128, 1), 256, G3_SMEM>>>(
            mt1_e, w1_e, nullptr, mff_e, FFD, DDIM, nullptr, BNUM);
        k_gemm3<<<dim3(DDIM / 128, 1), 256, G3_SMEM>>>(
            mff_e, w2_e, my_e, nullptr, DDIM, FFD, nullptr, BNUM);
    }

    // -- 5. mean scalars + final assembly --
    k_msum<<<1, 1024>>>(my, Wout, meanS, totalS);
    k_final2<<<MROWS / 8, 256>>>(cy, idx, pos, segoff, Wout, meanS, totalS, out);
}

// round 5
// speedup vs baseline: 4.7502x; 2.6395x over previous
#include <cuda_runtime.h>
#include <cuda_bf16.h>
#include <math.h>
#include <stdint.h>

// Problem constants
#define MROWS 8192      // B*S
#define DDIM  512
#define HNUM  8
#define KHD   64
#define FFD   2048
#define ENUM  4
#define SLEN  1024
#define BNUM  8
#define QKVW  1536
#define CROWS (MROWS + 128)   // compact rows + mean-row margin

// ===================== scratch (device globals) ==============================
__device__ __nv_bfloat16 g_xbf  [MROWS * 2 * DDIM];     // embedding, split
__device__ float         g_qkv  [MROWS * QKVW];         // shared qkv fp32
__device__ float         g_att  [MROWS * DDIM];         // shared attn out fp32 (gate)
__device__ __nv_bfloat16 g_attbf[MROWS * 2 * DDIM];     // shared attn out split
__device__ float         g_h    [MROWS * DDIM];         // shared block out fp32
__device__ int   g_idx[MROWS];
__device__ int   g_cnt[ENUM * BNUM];
__device__ int   g_segoff[ENUM * BNUM];
__device__ int   g_ne[ENUM];
__device__ int   g_pos[MROWS];
__device__ float g_meanS[ENUM * BNUM];
__device__ float g_totalS[BNUM];
__device__ float g_c2[FFD * ENUM];                       // W2@Wg
__device__ float g_c1[DDIM * ENUM];                      // W1@c2
__device__ float g_c0[DDIM * ENUM];                      // Wo@c1 (gate matrix)
__device__ __align__(16) unsigned char g_zerobuf[16];

// per-expert compact buffers
__device__ __nv_bfloat16 g_cbfA[ENUM * MROWS * 2 * DDIM];   // gathered h split
__device__ float         g_qkvc[ENUM * MROWS * QKVW];       // compact qkv fp32
__device__ __nv_bfloat16 g_catt[ENUM * CROWS * 2 * DDIM];   // compact attn + mean rows
__device__ float         g_cy  [ENUM * CROWS * DDIM];       // compact expert out

// weights: bf16 hi|lo split. *_T = transposed [N, 2K]; *_A = row-split [M, 2K]
__device__ __nv_bfloat16 g_swqkv[QKVW * 2 * DDIM];
__device__ __nv_bfloat16 g_sw1  [FFD  * 2 * DDIM];
__device__ __nv_bfloat16 g_sw2  [DDIM * 2 * FFD];
__device__ __nv_bfloat16 g_swoA [DDIM * 2 * DDIM];
__device__ __nv_bfloat16 g_scmb1[DDIM * 2 * FFD];        // Wo@W1 split [512, 2*2048]
__device__ __nv_bfloat16 g_scmbB[DDIM * 2 * DDIM];       // (Wo@W1@W2)^T-format
__device__ __nv_bfloat16 g_ewqkv[ENUM * QKVW * 2 * DDIM];
__device__ __nv_bfloat16 g_ew1  [ENUM * FFD  * 2 * DDIM];
__device__ __nv_bfloat16 g_ew2  [ENUM * DDIM * 2 * FFD];
__device__ __nv_bfloat16 g_ewoA [ENUM * DDIM * 2 * DDIM];
__device__ __nv_bfloat16 g_ecmb1[ENUM * DDIM * 2 * FFD];
__device__ __nv_bfloat16 g_ecmbB[ENUM * DDIM * 2 * DDIM];

// ===================== PTX helpers (base ISA only) ==========================
__device__ __forceinline__ uint32_t smem_u32(const void* p) {
    uint32_t a;
    asm("{ .reg .u64 t; cvta.to.shared.u64 t, %1; cvt.u32.u64 %0, t; }"
        : "=r"(a) : "l"(p));
    return a;
}
__device__ __forceinline__ void cp16(uint32_t dst, const void* src) {
    asm volatile("cp.async.cg.shared.global [%0], [%1], 16;"
                 :: "r"(dst), "l"(src) : "memory");
}
__device__ __forceinline__ void ldsm_x4(uint32_t& r0, uint32_t& r1,
                                        uint32_t& r2, uint32_t& r3, uint32_t addr) {
    asm volatile("ldmatrix.sync.aligned.m8n8.x4.shared.b16 {%0,%1,%2,%3}, [%4];"
                 : "=r"(r0), "=r"(r1), "=r"(r2), "=r"(r3) : "r"(addr));
}
__device__ __forceinline__ void mma16816(float* c, const uint32_t* a, const uint32_t* b) {
    asm volatile("mma.sync.aligned.m16n8k16.row.col.f32.bf16.bf16.f32 "
                 "{%0,%1,%2,%3}, {%4,%5,%6,%7}, {%8,%9}, {%0,%1,%2,%3};"
                 : "+f"(c[0]), "+f"(c[1]), "+f"(c[2]), "+f"(c[3])
                 : "r"(a[0]), "r"(a[1]), "r"(a[2]), "r"(a[3]),
                   "r"(b[0]), "r"(b[1]));
}
__device__ __forceinline__ void split_bf16(float x, __nv_bfloat16& hi, __nv_bfloat16& lo) {
    hi = __float2bfloat16(x);
    lo = __float2bfloat16(x - __bfloat162float(hi));
}

// ===================== embedding gather (split output) ======================
__global__ void k_gather(const int* __restrict__ tok,
                         const float* __restrict__ emb,
                         __nv_bfloat16* __restrict__ xbf)
{
    int t  = blockIdx.x * blockDim.x + threadIdx.x;
    int i  = t >> 7;
    int c4 = t & 127;
    float4 v = ((const float4*)(emb + (size_t)tok[i] * DDIM))[c4];
    float xv[4] = {v.x, v.y, v.z, v.w};
    __nv_bfloat16 hi[4], lo[4];
#pragma unroll
    for (int j = 0; j < 4; j++) split_bf16(xv[j], hi[j], lo[j]);
    __nv_bfloat16* row = xbf + (size_t)i * (2 * DDIM);
    *(uint64_t*)(row + c4 * 4)        = *(uint64_t*)hi;
    *(uint64_t*)(row + DDIM + c4 * 4) = *(uint64_t*)lo;
}

// ===================== weight conversion kernels ============================
// transpose + split: W [K,N] (stride wSz per z) -> Y [N, 2K]
__global__ void k_cvt_wt(const float* __restrict__ W, size_t wSz,
                         __nv_bfloat16* __restrict__ Y, size_t ySz,
                         int K, int N)
{
    W += (size_t)blockIdx.z * wSz;
    Y += (size_t)blockIdx.z * ySz;
    __shared__ float tile[32][33];
    int k0 = blockIdx.y * 32, n0 = blockIdx.x * 32;
    int tx = threadIdx.x, ty = threadIdx.y;   // 32 x 8
#pragma unroll
    for (int i = 0; i < 32; i += 8)
        tile[ty + i][tx] = W[(size_t)(k0 + ty + i) * N + n0 + tx];
    __syncthreads();
#pragma unroll
    for (int i = 0; i < 32; i += 8) {
        float x = tile[tx][ty + i];
        __nv_bfloat16 hi, lo; split_bf16(x, hi, lo);
        size_t base = (size_t)(n0 + ty + i) * (2 * K) + k0 + tx;
        Y[base]     = hi;
        Y[base + K] = lo;
    }
}

// row split, no transpose: W [M,512] -> Y [M, 1024]
__global__ void k_cvt_a(const float* __restrict__ W, size_t wSz,
                        __nv_bfloat16* __restrict__ Y, size_t ySz)
{
    W += (size_t)blockIdx.z * wSz;
    Y += (size_t)blockIdx.z * ySz;
    int t  = blockIdx.x * blockDim.x + threadIdx.x;
    int r  = t >> 7;
    int c4 = t & 127;
    float4 v = ((const float4*)(W + (size_t)r * DDIM))[c4];
    float xv[4] = {v.x, v.y, v.z, v.w};
    __nv_bfloat16 hi[4], lo[4];
#pragma unroll
    for (int j = 0; j < 4; j++) split_bf16(xv[j], hi[j], lo[j]);
    __nv_bfloat16* row = Y + (size_t)r * (2 * DDIM);
    *(uint64_t*)(row + c4 * 4)        = *(uint64_t*)hi;
    *(uint64_t*)(row + DDIM + c4 * 4) = *(uint64_t*)lo;
}

// ===================== mma.sync bf16x3 GEMM (z-batched, row-predicated) =====
#define G3_STAGE 16384
#define G3_SMEM  (3 * G3_STAGE)

__global__ __launch_bounds__(256)
void k_gemm3(const __nv_bfloat16* __restrict__ Ag, size_t aSz,
             const __nv_bfloat16* __restrict__ Bg, size_t bSz,
             float* __restrict__ Cf, size_t cSz,
             __nv_bfloat16* __restrict__ Y, size_t ySz,
             int N, int K,
             const int* __restrict__ nptr, int nconst, int nadd)
{
    const int z = blockIdx.z;
    Ag += (size_t)z * aSz;
    Bg += (size_t)z * bSz;
    const int n = (nptr ? __ldg(nptr + z) : nconst) + nadd;
    const int mbase = blockIdx.y * 128;
    if (mbase >= n) return;
    if (Cf) Cf += (size_t)z * cSz;
    if (Y)  Y  += (size_t)z * ySz;

    extern __shared__ __align__(128) unsigned char smem[];
    const uint32_t sbase = smem_u32(smem);
    const int tid  = threadIdx.x;
    const int wid  = tid >> 5;
    const int lane = tid & 31;

    const int nbase = blockIdx.x * 128;
    const int K2    = 2 * K;
    const int NCP   = K / 32;
    const int NC    = 3 * NCP;

    const int mo = (wid >> 2) * 64;
    const int no = (wid & 3) * 32;

    auto fill = [&](int c) {
        int s  = c % 3;
        int p  = c / NCP, ck = c - p * NCP;
        int acol = ((p == 2) ? K : 0) + ck * 32;
        int bcol = ((p == 1) ? K : 0) + ck * 32;
        uint32_t sAo = sbase + s * G3_STAGE;
        uint32_t sBo = sAo + 8192;
#pragma unroll
        for (int i2 = 0; i2 < 2; i2++) {
            int ch = tid + i2 * 256;
            int r  = ch >> 2, cc = ch & 3;
            uint32_t sw = (uint32_t)((cc ^ ((r >> 1) & 3)) << 4);
            const void* asrc = (mbase + r < n)
                ? (const void*)(Ag + (size_t)(mbase + r) * K2 + acol + cc * 8)
                : (const void*)g_zerobuf;
            cp16(sAo + r * 64 + sw, asrc);
            cp16(sBo + r * 64 + sw, Bg + (size_t)(nbase + r) * K2 + bcol + cc * 8);
        }
        asm volatile("cp.async.commit_group;" ::: "memory");
    };

    float acc[4][4][4];
#pragma unroll
    for (int i = 0; i < 4; i++)
#pragma unroll
        for (int j = 0; j < 4; j++)
#pragma unroll
            for (int t = 0; t < 4; t++) acc[i][j][t] = 0.0f;

    fill(0);
    fill(1);

    for (int c = 0; c < NC; c++) {
        if (c + 1 < NC) asm volatile("cp.async.wait_group 1;" ::: "memory");
        else            asm volatile("cp.async.wait_group 0;" ::: "memory");
        __syncthreads();

        uint32_t sAo = sbase + (c % 3) * G3_STAGE;
        uint32_t sBo = sAo + 8192;

#pragma unroll
        for (int kk = 0; kk < 2; kk++) {
            uint32_t a[4][4];
#pragma unroll
            for (int i = 0; i < 4; i++) {
                int row = mo + i * 16 + (lane & 15);
                int chk = 2 * kk + (lane >> 4);
                uint32_t addr = sAo + row * 64 + (uint32_t)(((chk ^ ((row >> 1) & 3))) << 4);
                ldsm_x4(a[i][0], a[i][1], a[i][2], a[i][3], addr);
            }
            uint32_t b[4][2];
#pragma unroll
            for (int jj = 0; jj < 2; jj++) {
                int nrow = no + jj * 16 + (lane & 7) + ((lane >> 4) << 3);
                int chk  = 2 * kk + ((lane >> 3) & 1);
                uint32_t addr = sBo + nrow * 64 + (uint32_t)(((chk ^ ((nrow >> 1) & 3))) << 4);
                ldsm_x4(b[2 * jj][0], b[2 * jj][1], b[2 * jj + 1][0], b[2 * jj + 1][1], addr);
            }
#pragma unroll
            for (int i = 0; i < 4; i++)
#pragma unroll
                for (int j = 0; j < 4; j++)
                    mma16816(acc[i][j], a[i], b[j]);
        }

        __syncthreads();
        if (c + 2 < NC) fill(c + 2);
    }

    int rbase = mbase + mo + (lane >> 2);
    int cbase = nbase + no + (lane & 3) * 2;
#pragma unroll
    for (int i = 0; i < 4; i++) {
        int r0 = rbase + i * 16, r1 = r0 + 8;
#pragma unroll
        for (int j = 0; j < 4; j++) {
            int col = cbase + j * 8;
            if (Cf) {
                if (r0 < n)
                    *(float2*)(Cf + (size_t)r0 * N + col) = make_float2(acc[i][j][0], acc[i][j][1]);
                if (r1 < n)
                    *(float2*)(Cf + (size_t)r1 * N + col) = make_float2(acc[i][j][2], acc[i][j][3]);
            }
            if (Y) {
                if (r0 < n) {
                    __nv_bfloat16 h0, l0, h1, l1;
                    split_bf16(acc[i][j][0], h0, l0);
                    split_bf16(acc[i][j][1], h1, l1);
                    *(__nv_bfloat162*)(Y + (size_t)r0 * 2 * N + col)     = __halves2bfloat162(h0, h1);
                    *(__nv_bfloat162*)(Y + (size_t)r0 * 2 * N + N + col) = __halves2bfloat162(l0, l1);
                }
                if (r1 < n) {
                    __nv_bfloat16 h0, l0, h1, l1;
                    split_bf16(acc[i][j][2], h0, l0);
                    split_bf16(acc[i][j][3], h1, l1);
                    *(__nv_bfloat162*)(Y + (size_t)r1 * 2 * N + col)     = __halves2bfloat162(h0, h1);
                    *(__nv_bfloat162*)(Y + (size_t)r1 * 2 * N + N + col) = __halves2bfloat162(l0, l1);
                }
            }
        }
    }
}

// ===================== dense flash attention (fp32 + split outputs) ========
__global__ __launch_bounds__(128)
void k_attn(const float* __restrict__ QKV, float* __restrict__ O,
            __nv_bfloat16* __restrict__ Oy)
{
    const int KT = 32;
    __shared__ float Ks[KT][KHD];
    __shared__ float Vs[KT][KHD];

    int bh = blockIdx.y;
    int b  = bh / HNUM, h = bh % HNUM;
    int qrow = blockIdx.x * 128 + threadIdx.x;

    const float* qptr = QKV + (size_t)(b * SLEN + qrow) * QKVW + h * KHD;
    float q[KHD];
#pragma unroll
    for (int d = 0; d < KHD; d++) q[d] = qptr[d] * 0.125f;

    float o[KHD];
#pragma unroll
    for (int d = 0; d < KHD; d++) o[d] = 0.0f;
    float m = -INFINITY, l = 0.0f;

    for (int kt = 0; kt < SLEN; kt += KT) {
#pragma unroll
        for (int it = 0; it < (KT * KHD) / (128 * 4); it++) {
            int idx = (it * 128 + threadIdx.x) * 4;
            int r = idx >> 6, c = idx & 63;
            size_t off = (size_t)(b * SLEN + kt + r) * QKVW + h * KHD + c;
            *(float4*)&Ks[r][c] = *(const float4*)(QKV + off + DDIM);
            *(float4*)&Vs[r][c] = *(const float4*)(QKV + off + 2 * DDIM);
        }
        __syncthreads();

        float s[KT];
#pragma unroll
        for (int j = 0; j < KT; j++) {
            float a = 0.0f;
#pragma unroll
            for (int d = 0; d < KHD; d++) a = fmaf(q[d], Ks[j][d], a);
            s[j] = a;
        }
        float tmax = s[0];
#pragma unroll
        for (int j = 1; j < KT; j++) tmax = fmaxf(tmax, s[j]);
        float mnew = fmaxf(m, tmax);
        float corr = __expf(m - mnew);
        l *= corr;
#pragma unroll
        for (int d = 0; d < KHD; d++) o[d] *= corr;
#pragma unroll
        for (int j = 0; j < KT; j++) {
            float p = __expf(s[j] - mnew);
            l += p;
#pragma unroll
            for (int d = 0; d < KHD; d++) o[d] = fmaf(p, Vs[j][d], o[d]);
        }
        m = mnew;
        __syncthreads();
    }

    float inv = 1.0f / l;
    size_t row = (size_t)(b * SLEN + qrow);
    float* op = O + row * DDIM + h * KHD;
    __nv_bfloat16* yb = Oy + row * (2 * DDIM) + h * KHD;
#pragma unroll
    for (int d = 0; d < KHD; d += 2) {
        float v0 = o[d] * inv, v1 = o[d + 1] * inv;
        *(float2*)(op + d) = make_float2(v0, v1);
        __nv_bfloat16 h0, l0, h1, l1;
        split_bf16(v0, h0, l0);
        split_bf16(v1, h1, l1);
        *(__nv_bfloat162*)(yb + d)        = __halves2bfloat162(h0, h1);
        *(__nv_bfloat162*)(yb + DDIM + d) = __halves2bfloat162(l0, l1);
    }
}

// ===================== compact expert attention (z-batched) =================
__global__ __launch_bounds__(128)
void k_attn_c(const float* __restrict__ qkvc,
              __nv_bfloat16* __restrict__ cattc,
              const int* __restrict__ cnt32, const int* __restrict__ seg32)
{
    const int KT = 32;
    __shared__ float Ks[KT][KHD];
    __shared__ float Vs[KT][KHD];

    int e  = blockIdx.z;
    int bh = blockIdx.y;
    int b  = bh / HNUM, h = bh % HNUM;
    int cnt = __ldg(cnt32 + e * BNUM + b), seg = __ldg(seg32 + e * BNUM + b);
    if (blockIdx.x * 128 >= cnt) return;
    int qidx = blockIdx.x * 128 + threadIdx.x;
    bool qact = qidx < cnt;

    const float* QKV = qkvc + (size_t)e * MROWS * QKVW;
    __nv_bfloat16* Oy = cattc + (size_t)e * CROWS * (2 * DDIM);

    const float* qptr = QKV + (size_t)(seg + (qact ? qidx : 0)) * QKVW + h * KHD;
    float q[KHD];
#pragma unroll
    for (int d = 0; d < KHD; d++) q[d] = qptr[d] * 0.125f;

    float o[KHD];
#pragma unroll
    for (int d = 0; d < KHD; d++) o[d] = 0.0f;
    float m = 0.0f;                       // virtual masked keys: logit 0
    float l = (float)(SLEN - cnt);

    for (int kt = 0; kt < cnt; kt += KT) {
        int nval = cnt - kt; if (nval > KT) nval = KT;
#pragma unroll
        for (int it = 0; it < (KT * KHD) / (128 * 4); it++) {
            int idx = (it * 128 + threadIdx.x) * 4;
            int r = idx >> 6, c = idx & 63;
            if (r < nval) {
                size_t off = (size_t)(seg + kt + r) * QKVW + h * KHD + c;
                *(float4*)&Ks[r][c] = *(const float4*)(QKV + off + DDIM);
                *(float4*)&Vs[r][c] = *(const float4*)(QKV + off + 2 * DDIM);
            } else {
                *(float4*)&Ks[r][c] = make_float4(0.f, 0.f, 0.f, 0.f);
                *(float4*)&Vs[r][c] = make_float4(0.f, 0.f, 0.f, 0.f);
            }
        }
        __syncthreads();

        float s[KT];
#pragma unroll
        for (int j = 0; j < KT; j++) {
            float a = 0.0f;
#pragma unroll
            for (int d = 0; d < KHD; d++) a = fmaf(q[d], Ks[j][d], a);
            s[j] = (j < nval) ? a : -1e30f;
        }
        float tmax = s[0];
#pragma unroll
        for (int j = 1; j < KT; j++) tmax = fmaxf(tmax, s[j]);
        float mnew = fmaxf(m, tmax);
        float corr = __expf(m - mnew);
        l *= corr;
#pragma unroll
        for (int d = 0; d < KHD; d++) o[d] *= corr;
#pragma unroll
        for (int j = 0; j < KT; j++) {
            float p = __expf(s[j] - mnew);
            l += p;
#pragma unroll
            for (int d = 0; d < KHD; d++) o[d] = fmaf(p, Vs[j][d], o[d]);
        }
        m = mnew;
        __syncthreads();
    }

    if (qact) {
        float inv = 1.0f / l;
        __nv_bfloat16* yrow = Oy + (size_t)(seg + qidx) * (2 * DDIM) + h * KHD;
#pragma unroll
        for (int d = 0; d < KHD; d += 2) {
            float v0 = o[d] * inv, v1 = o[d + 1] * inv;
            __nv_bfloat16 h0, l0, h1, l1;
            split_bf16(v0, h0, l0);
            split_bf16(v1, h1, l1);
            *(__nv_bfloat162*)(yrow + d)        = __halves2bfloat162(h0, h1);
            *(__nv_bfloat162*)(yrow + DDIM + d) = __halves2bfloat162(l0, l1);
        }
    }
}

// ===================== small fp32 GEMM: O[M,4] = A[M,K] @ B4[K,4] ===========
__global__ void k_mat4(const float* __restrict__ A, const float* __restrict__ B4,
                       float* __restrict__ O4, int K)
{
    int m = blockIdx.x * 8 + (threadIdx.x >> 5);
    int lane = threadIdx.x & 31;
    const float* ar = A + (size_t)m * K;
    float a0 = 0.f, a1 = 0.f, a2 = 0.f, a3 = 0.f;
    for (int k = lane; k < K; k += 32) {
        float a = ar[k];
        float4 b = *(const float4*)(B4 + (size_t)k * 4);
        a0 = fmaf(a, b.x, a0); a1 = fmaf(a, b.y, a1);
        a2 = fmaf(a, b.z, a2); a3 = fmaf(a, b.w, a3);
    }
#pragma unroll
    for (int off = 16; off; off >>= 1) {
        a0 += __shfl_down_sync(0xffffffffu, a0, off);
        a1 += __shfl_down_sync(0xffffffffu, a1, off);
        a2 += __shfl_down_sync(0xffffffffu, a2, off);
        a3 += __shfl_down_sync(0xffffffffu, a3, off);
    }
    if (lane == 0)
        *(float4*)(O4 + (size_t)m * 4) = make_float4(a0, a1, a2, a3);
}

// ===================== gate argmax (att @ c0) ===============================
__global__ void k_gate(const float* __restrict__ Hm, const float* __restrict__ Wg,
                       int* __restrict__ idx)
{
    int warp = (blockIdx.x * blockDim.x + threadIdx.x) >> 5;
    int lane = threadIdx.x & 31;
    if (warp >= MROWS) return;
    const float* hr = Hm + (size_t)warp * DDIM;
    float g[ENUM] = {0, 0, 0, 0};
    for (int d = lane; d < DDIM; d += 32) {
        float hv = hr[d];
#pragma unroll
        for (int e = 0; e < ENUM; e++) g[e] = fmaf(hv, Wg[d * ENUM + e], g[e]);
    }
#pragma unroll
    for (int e = 0; e < ENUM; e++)
#pragma unroll
        for (int off = 16; off; off >>= 1)
            g[e] += __shfl_down_sync(0xffffffff, g[e], off);
    if (lane == 0) {
        int best = 0; float bv = g[0];
#pragma unroll
        for (int e = 1; e < ENUM; e++)
            if (g[e] > bv) { bv = g[e]; best = e; }
        idx[warp] = best;
    }
}

// ===================== compaction: scan / offsets / gather ==================
__global__ __launch_bounds__(1024)
void k_scan(const int* __restrict__ idx, int* __restrict__ pos, int* __restrict__ cnt)
{
    int e = blockIdx.x, b = blockIdx.y;
    int t = threadIdx.x;
    int token = b * SLEN + t;
    int p = (idx[token] == e) ? 1 : 0;
    int v = p;
#pragma unroll
    for (int o = 1; o < 32; o <<= 1) {
        int u = __shfl_up_sync(0xffffffffu, v, o);
        if ((t & 31) >= o) v += u;
    }
    __shared__ int wsum[32];
    if ((t & 31) == 31) wsum[t >> 5] = v;
    __syncthreads();
    if (t < 32) {
        int w = wsum[t];
#pragma unroll
        for (int o = 1; o < 32; o <<= 1) {
            int u = __shfl_up_sync(0xffffffffu, w, o);
            if (t >= o) w += u;
        }
        wsum[t] = w;
    }
    __syncthreads();
    int incl = v + ((t >= 32) ? wsum[(t >> 5) - 1] : 0);
    if (p) pos[token] = incl - 1;
    if (t == 1023) cnt[e * BNUM + b] = incl;
}

__global__ void k_off(const int* __restrict__ cnt, int* __restrict__ segoff,
                      int* __restrict__ ne)
{
    int e = threadIdx.x;
    if (e < ENUM) {
        int s = 0;
        for (int b = 0; b < BNUM; b++) { segoff[e * BNUM + b] = s; s += cnt[e * BNUM + b]; }
        ne[e] = s;
    }
}

__global__ void k_gatherc(const float* __restrict__ h, const int* __restrict__ idx,
                          const int* __restrict__ pos, const int* __restrict__ segoff,
                          __nv_bfloat16* __restrict__ cbf)
{
    int t = blockIdx.x * blockDim.x + threadIdx.x;
    int i = t >> 7, c4 = t & 127;
    int e = idx[i], b = i / SLEN;
    int slot = segoff[e * BNUM + b] + pos[i];
    float4 x = ((const float4*)(h + (size_t)i * DDIM))[c4];
    float xv[4] = {x.x, x.y, x.z, x.w};
    __nv_bfloat16 hi[4], lo[4];
#pragma unroll
    for (int j = 0; j < 4; j++) split_bf16(xv[j], hi[j], lo[j]);
    __nv_bfloat16* row = cbf + ((size_t)e * MROWS + slot) * (2 * DDIM);
    *(uint64_t*)(row + c4 * 4)        = *(uint64_t*)hi;
    *(uint64_t*)(row + DDIM + c4 * 4) = *(uint64_t*)lo;
}

// ===================== mean-v rows (appended to catt) =======================
__global__ __launch_bounds__(128)
void k_meanv(const float* __restrict__ qkvc, const int* __restrict__ cnt32,
             const int* __restrict__ seg32, const int* __restrict__ ne,
             __nv_bfloat16* __restrict__ cattc)
{
    int b = blockIdx.x, e = blockIdx.y;
    int cnt = __ldg(cnt32 + e * BNUM + b), seg = __ldg(seg32 + e * BNUM + b);
    const float* QKV = qkvc + (size_t)e * MROWS * QKVW;
    int c = threadIdx.x * 4;
    float4 s = make_float4(0.f, 0.f, 0.f, 0.f);
    for (int r = 0; r < cnt; r++) {
        float4 v = *(const float4*)(QKV + (size_t)(seg + r) * QKVW + 2 * DDIM + c);
        s.x += v.x; s.y += v.y; s.z += v.z; s.w += v.w;
    }
    const float is = 1.0f / (float)SLEN;
    float vv[4] = {s.x * is, s.y * is, s.z * is, s.w * is};
    int target = __ldg(ne + e) + b;
    __nv_bfloat16* row = cattc + ((size_t)e * CROWS + target) * (2 * DDIM);
#pragma unroll
    for (int j = 0; j < 4; j++) {
        __nv_bfloat16 hi, lo; split_bf16(vv[j], hi, lo);
        row[c + j]        = hi;
        row[DDIM + c + j] = lo;
    }
}

// ===================== mean scalars =========================================
__global__ __launch_bounds__(1024)
void k_msum(const float* __restrict__ cy, const int* __restrict__ ne,
            const float* __restrict__ Wout,
            float* __restrict__ meanS, float* __restrict__ totalS)
{
    __shared__ float sh[ENUM * BNUM];
    int w = threadIdx.x >> 5, lane = threadIdx.x & 31;   // w = e*8+b
    int e = w >> 3, b = w & 7;
    const float* row = cy + ((size_t)e * CROWS + __ldg(ne + e) + b) * DDIM;
    float s = 0.0f;
    for (int d = lane; d < DDIM; d += 32) s = fmaf(row[d], Wout[d], s);
#pragma unroll
    for (int off = 16; off; off >>= 1) s += __shfl_down_sync(0xffffffff, s, off);
    if (lane == 0) { sh[w] = s; meanS[w] = s; }
    __syncthreads();
    if (threadIdx.x < BNUM) {
        float t = 0.0f;
        for (int e2 = 0; e2 < ENUM; e2++) t += sh[e2 * BNUM + threadIdx.x];
        totalS[threadIdx.x] = t;
    }
}

// ===================== final: dot + mean corrections ========================
__global__ void k_final2(const float* __restrict__ cy, const int* __restrict__ idx,
                         const int* __restrict__ pos, const int* __restrict__ segoff,
                         const float* __restrict__ Wout, const float* __restrict__ meanS,
                         const float* __restrict__ totalS, float* __restrict__ out)
{
    int warp = (blockIdx.x * blockDim.x + threadIdx.x) >> 5;
    int lane = threadIdx.x & 31;
    if (warp >= MROWS) return;
    int e = idx[warp], b = warp / SLEN;
    int slot = segoff[e * BNUM + b] + pos[warp];
    const float* r = cy + ((size_t)e * CROWS + slot) * DDIM;
    float s = 0.0f;
    for (int d = lane; d < DDIM; d += 32) s = fmaf(r[d], Wout[d], s);
#pragma unroll
    for (int off = 16; off; off >>= 1) s += __shfl_down_sync(0xffffffff, s, off);
    if (lane == 0) out[warp] = s + totalS[b] - meanS[e * BNUM + b];
}

// ===================== host orchestration ===================================
extern "C" void kernel_launch(void* const* d_in, const int* in_sizes, int n_in,
                              void* d_out, int out_size)
{
    (void)in_sizes; (void)n_in; (void)out_size;
    const int*   tokens = (const int*)  d_in[0];
    const float* emb    = (const float*)d_in[1];
    const float* Wq     = (const float*)d_in[2];
    const float* Wk     = (const float*)d_in[3];
    const float* Wv     = (const float*)d_in[4];
    const float* Wo     = (const float*)d_in[5];
    const float* W1     = (const float*)d_in[6];
    const float* W2     = (const float*)d_in[7];
    const float* Wg     = (const float*)d_in[8];
    const float* eWq    = (const float*)d_in[9];
    const float* eWk    = (const float*)d_in[10];
    const float* eWv    = (const float*)d_in[11];
    const float* eWo    = (const float*)d_in[12];
    const float* eW1    = (const float*)d_in[13];
    const float* eW2    = (const float*)d_in[14];
    const float* Wout   = (const float*)d_in[15];
    float* out = (float*)d_out;

    __nv_bfloat16 *xbf, *attbf, *cbfA, *catt, *swqkv, *sw1, *sw2, *swoA, *scmb1, *scmbB;
    __nv_bfloat16 *ewqkv, *ew1, *ew2, *ewoA, *ecmb1, *ecmbB;
    float *qkv, *att, *h, *qkvc, *cy, *meanS, *totalS, *c2, *c1, *c0;
    int *idx, *cnt, *segoff, *ne, *pos;
    cudaGetSymbolAddress((void**)&xbf,    g_xbf);
    cudaGetSymbolAddress((void**)&qkv,    g_qkv);
    cudaGetSymbolAddress((void**)&att,    g_att);
    cudaGetSymbolAddress((void**)&attbf,  g_attbf);
    cudaGetSymbolAddress((void**)&h,      g_h);
    cudaGetSymbolAddress((void**)&idx,    g_idx);
    cudaGetSymbolAddress((void**)&cnt,    g_cnt);
    cudaGetSymbolAddress((void**)&segoff, g_segoff);
    cudaGetSymbolAddress((void**)&ne,     g_ne);
    cudaGetSymbolAddress((void**)&pos,    g_pos);
    cudaGetSymbolAddress((void**)&meanS,  g_meanS);
    cudaGetSymbolAddress((void**)&totalS, g_totalS);
    cudaGetSymbolAddress((void**)&c2,     g_c2);
    cudaGetSymbolAddress((void**)&c1,     g_c1);
    cudaGetSymbolAddress((void**)&c0,     g_c0);
    cudaGetSymbolAddress((void**)&cbfA,   g_cbfA);
    cudaGetSymbolAddress((void**)&qkvc,   g_qkvc);
    cudaGetSymbolAddress((void**)&catt,   g_catt);
    cudaGetSymbolAddress((void**)&cy,     g_cy);
    cudaGetSymbolAddress((void**)&swqkv,  g_swqkv);
    cudaGetSymbolAddress((void**)&sw1,    g_sw1);
    cudaGetSymbolAddress((void**)&sw2,    g_sw2);
    cudaGetSymbolAddress((void**)&swoA,   g_swoA);
    cudaGetSymbolAddress((void**)&scmb1,  g_scmb1);
    cudaGetSymbolAddress((void**)&scmbB,  g_scmbB);
    cudaGetSymbolAddress((void**)&ewqkv,  g_ewqkv);
    cudaGetSymbolAddress((void**)&ew1,    g_ew1);
    cudaGetSymbolAddress((void**)&ew2,    g_ew2);
    cudaGetSymbolAddress((void**)&ewoA,   g_ewoA);
    cudaGetSymbolAddress((void**)&ecmb1,  g_ecmb1);
    cudaGetSymbolAddress((void**)&ecmbB,  g_ecmbB);

    cudaFuncSetAttribute(k_gemm3, cudaFuncAttributeMaxDynamicSharedMemorySize, G3_SMEM);

    dim3 tb32(32, 8);
    const size_t WQKV_SZ = (size_t)QKVW * 2 * DDIM;
    const size_t W1_SZ   = (size_t)FFD  * 2 * DDIM;
    const size_t W2_SZ   = (size_t)DDIM * 2 * FFD;
    const size_t WO_SZ   = (size_t)DDIM * 2 * DDIM;

    // ---- weight conversions ----
    // shared
    k_cvt_wt<<<dim3(DDIM / 32, DDIM / 32, 1), tb32>>>(Wq, 0, swqkv, 0, DDIM, DDIM);
    k_cvt_wt<<<dim3(DDIM / 32, DDIM / 32, 1), tb32>>>(Wk, 0, swqkv + WO_SZ, 0, DDIM, DDIM);
    k_cvt_wt<<<dim3(DDIM / 32, DDIM / 32, 1), tb32>>>(Wv, 0, swqkv + 2 * WO_SZ, 0, DDIM, DDIM);
    k_cvt_wt<<<dim3(FFD / 32, DDIM / 32, 1), tb32>>>(W1, 0, sw1, 0, DDIM, FFD);
    k_cvt_wt<<<dim3(DDIM / 32, FFD / 32, 1), tb32>>>(W2, 0, sw2, 0, FFD, DDIM);
    k_cvt_a<<<dim3(256, 1, 1), 256>>>(Wo, 0, swoA, 0);
    // experts (z = 4)
    k_cvt_wt<<<dim3(DDIM / 32, DDIM / 32, ENUM), tb32>>>(eWq, (size_t)DDIM * DDIM, ewqkv, WQKV_SZ, DDIM, DDIM);
    k_cvt_wt<<<dim3(DDIM / 32, DDIM / 32, ENUM), tb32>>>(eWk, (size_t)DDIM * DDIM, ewqkv + WO_SZ, WQKV_SZ, DDIM, DDIM);
    k_cvt_wt<<<dim3(DDIM / 32, DDIM / 32, ENUM), tb32>>>(eWv, (size_t)DDIM * DDIM, ewqkv + 2 * WO_SZ, WQKV_SZ, DDIM, DDIM);
    k_cvt_wt<<<dim3(FFD / 32, DDIM / 32, ENUM), tb32>>>(eW1, (size_t)DDIM * FFD, ew1, W1_SZ, DDIM, FFD);
    k_cvt_wt<<<dim3(DDIM / 32, FFD / 32, ENUM), tb32>>>(eW2, (size_t)FFD * DDIM, ew2, W2_SZ, FFD, DDIM);
    k_cvt_a<<<dim3(256, 1, ENUM), 256>>>(eWo, (size_t)DDIM * DDIM, ewoA, WO_SZ);

    // ---- weight combos: cmbB = (Wo@W1@W2)^T-format, via two bf16x3 GEMMs ----
    k_gemm3<<<dim3(FFD / 128, 4, 1), 256, G3_SMEM>>>(
        swoA, 0, sw1, 0, nullptr, 0, scmb1, 0, FFD, DDIM, nullptr, DDIM, 0);
    k_gemm3<<<dim3(DDIM / 128, 4, 1), 256, G3_SMEM>>>(
        sw2, 0, scmb1, 0, nullptr, 0, scmbB, 0, DDIM, FFD, nullptr, DDIM, 0);
    k_gemm3<<<dim3(FFD / 128, 4, ENUM), 256, G3_SMEM>>>(
        ewoA, WO_SZ, ew1, W1_SZ, nullptr, 0, ecmb1, W2_SZ, FFD, DDIM, nullptr, DDIM, 0);
    k_gemm3<<<dim3(DDIM / 128, 4, ENUM), 256, G3_SMEM>>>(
        ew2, W2_SZ, ecmb1, W2_SZ, nullptr, 0, ecmbB, WO_SZ, DDIM, FFD, nullptr, DDIM, 0);

    // ---- gate combo matrix c0 = Wo@(W1@(W2@Wg)) in exact fp32 ----
    k_mat4<<<FFD / 8, 256>>>(W2, Wg, c2, DDIM);
    k_mat4<<<DDIM / 8, 256>>>(W1, c2, c1, FFD);
    k_mat4<<<DDIM / 8, 256>>>(Wo, c1, c0, DDIM);

    // ---- 1. embedding gather (split) ----
    k_gather<<<(MROWS * (DDIM / 4)) / 256, 256>>>(tokens, emb, xbf);

    // ---- 2. shared block ----
    k_gemm3<<<dim3(QKVW / 128, MROWS / 128, 1), 256, G3_SMEM>>>(
        xbf, 0, swqkv, 0, qkv, 0, nullptr, 0, QKVW, DDIM, nullptr, MROWS, 0);
    k_attn<<<dim3(SLEN / 128, BNUM * HNUM), 128>>>(qkv, att, attbf);

    // ---- 3. gate + compaction (from att, independent of h) ----
    k_gate<<<MROWS / 8, 256>>>(att, c0, idx);
    k_scan<<<dim3(ENUM, BNUM), 1024>>>(idx, pos, cnt);
    k_off<<<1, 32>>>(cnt, segoff, ne);

    // ---- 4. h = att @ (Wo@W1@W2), then gather into compact split layout ----
    k_gemm3<<<dim3(DDIM / 128, MROWS / 128, 1), 256, G3_SMEM>>>(
        attbf, 0, scmbB, 0, h, 0, nullptr, 0, DDIM, DDIM, nullptr, MROWS, 0);
    k_gatherc<<<(MROWS * (DDIM / 4)) / 256, 256>>>(h, idx, pos, segoff, cbfA);

    // ---- 5. experts, fully z-batched ----
    k_gemm3<<<dim3(QKVW / 128, MROWS / 128, ENUM), 256, G3_SMEM>>>(
        cbfA, (size_t)MROWS * 2 * DDIM, ewqkv, WQKV_SZ,
        qkvc, (size_t)MROWS * QKVW, nullptr, 0, QKVW, DDIM, ne, 0, 0);
    k_attn_c<<<dim3(SLEN / 128, BNUM * HNUM, ENUM), 128>>>(qkvc, catt, cnt, segoff);
    k_meanv<<<dim3(BNUM, ENUM), 128>>>(qkvc, cnt, segoff, ne, catt);
    k_gemm3<<<dim3(DDIM / 128, CROWS / 128, ENUM), 256, G3_SMEM>>>(
        catt, (size_t)CROWS * 2 * DDIM, ecmbB, WO_SZ,
        cy, (size_t)CROWS * DDIM, nullptr, 0, DDIM, DDIM, ne, 0, 8);

    // ---- 6. mean scalars + final assembly ----
    k_msum<<<1, 1024>>>(cy, ne, Wout, meanS, totalS);
    k_final2<<<MROWS / 8, 256>>>(cy, idx, pos, segoff, Wout, meanS, totalS, out);
}